// round 1
// baseline (speedup 1.0000x reference)
#include <cuda_runtime.h>
#include <math.h>

// PaiNN interaction layer, fused per-edge-tile kernel (fp32 SIMT baseline).
//
// Inputs (metadata order):
// 0 s [N,128] f32, 1 v [N,3,128] f32, 2 pos [N,3] f32, 3 edge_index [2,E] int32-or-int64,
// 4 W1 [276,256], 5 b1 [256], 6 W2 [256,256], 7 b2 [256],
// 8 Ws [256,128], 9 bs [128], 10 Wv [256,128], 11 bv [128],
// 12 centers [20], 13 widths [20]
// Output: concat(s_out [N,128], v_out [N,3,128]) f32.

#define FDIM 128
#define NRBF 20
#define IN_DIM (2 * FDIM + NRBF)   // 276
#define KPAD 280                   // IN_DIM padded to multiple of 8
#define HDIM 256
#define TILE_E 64
#define NTHREADS 256
#define KT 8

__device__ int g_idx64;

// Detect whether edge_index is int64 (little-endian high words all zero) or int32.
__global__ void detect_idx_kernel(const int* __restrict__ idx32) {
    __shared__ int nz;
    if (threadIdx.x == 0) nz = 0;
    __syncthreads();
    int v = idx32[2 * threadIdx.x + 1];   // first 256 odd int32 words (in-bounds either way)
    if (v != 0) atomicOr(&nz, 1);
    __syncthreads();
    if (threadIdx.x == 0) g_idx64 = (nz == 0) ? 1 : 0;
}

__global__ void init_out_kernel(const float4* __restrict__ s,
                                const float4* __restrict__ v,
                                float4* __restrict__ out, int ns4, int nv4) {
    int stride = gridDim.x * blockDim.x;
    for (int i = blockIdx.x * blockDim.x + threadIdx.x; i < ns4; i += stride)
        out[i] = s[i];
    for (int i = blockIdx.x * blockDim.x + threadIdx.x; i < nv4; i += stride)
        out[ns4 + i] = v[i];
}

__device__ __forceinline__ long long load_idx(const void* p, long long i, int is64) {
    if (is64) return ((const long long*)p)[i];
    return (long long)((const int*)p)[i];
}

__device__ __forceinline__ float silu(float x) {
    return x / (1.0f + __expf(-x));
}

// Tiled GEMM: acc[8][8] += Asm[64,Ktot](lda) @ W[Ktot,256], W staged through Bs[KT][256].
// MODE 0: W1 with zero-padded rows >= IN_DIM. MODE 1: plain [K,256]. MODE 2: [Ws|Wv] concat.
template <int MODE>
__device__ __forceinline__ void gemm_tile(const float* __restrict__ Asm, int lda, int Ktot,
                                          const float* __restrict__ Wg0,
                                          const float* __restrict__ Wg1,
                                          float* __restrict__ Bs,
                                          float acc[8][8], int m0, int n0, int tid) {
    for (int k0 = 0; k0 < Ktot; k0 += KT) {
        __syncthreads();  // previous compute done before Bs overwrite
        int krow = k0 + (tid >> 5);
        int col0 = (tid & 31) * 8;
        float4 w0, w1;
        if (MODE == 0) {
            if (krow < IN_DIM) {
                w0 = *(const float4*)(Wg0 + (long long)krow * HDIM + col0);
                w1 = *(const float4*)(Wg0 + (long long)krow * HDIM + col0 + 4);
            } else {
                w0 = make_float4(0.f, 0.f, 0.f, 0.f);
                w1 = w0;
            }
        } else if (MODE == 1) {
            w0 = *(const float4*)(Wg0 + (long long)krow * HDIM + col0);
            w1 = *(const float4*)(Wg0 + (long long)krow * HDIM + col0 + 4);
        } else {
            const float* Wsel = (col0 < FDIM)
                                    ? (Wg0 + (long long)krow * FDIM + col0)
                                    : (Wg1 + (long long)krow * FDIM + (col0 - FDIM));
            w0 = *(const float4*)(Wsel);
            w1 = *(const float4*)(Wsel + 4);
        }
        *(float4*)(Bs + (tid >> 5) * HDIM + col0) = w0;
        *(float4*)(Bs + (tid >> 5) * HDIM + col0 + 4) = w1;
        __syncthreads();
#pragma unroll
        for (int kk = 0; kk < KT; ++kk) {
            float a[8], b[8];
#pragma unroll
            for (int i = 0; i < 8; ++i) a[i] = Asm[(m0 + i) * lda + k0 + kk];  // broadcast LDS
#pragma unroll
            for (int j = 0; j < 8; j += 4) {
                float4 t = *(const float4*)(Bs + kk * HDIM + n0 + j);
                b[j] = t.x; b[j + 1] = t.y; b[j + 2] = t.z; b[j + 3] = t.w;
            }
#pragma unroll
            for (int i = 0; i < 8; ++i)
#pragma unroll
                for (int j = 0; j < 8; ++j) acc[i][j] += a[i] * b[j];
        }
    }
    __syncthreads();
}

__global__ __launch_bounds__(NTHREADS, 1)
void painn_edge_kernel(const float* __restrict__ s,
                       const float* __restrict__ pos,
                       const void* __restrict__ eidx,
                       const float* __restrict__ W1, const float* __restrict__ b1,
                       const float* __restrict__ W2, const float* __restrict__ b2,
                       const float* __restrict__ Ws, const float* __restrict__ bs,
                       const float* __restrict__ Wv, const float* __restrict__ bv,
                       const float* __restrict__ centers, const float* __restrict__ widths,
                       float* __restrict__ out_s, float* __restrict__ out_v,
                       int E, int N) {
    extern __shared__ float smem[];
    float* A    = smem;                       // [64][280] layer-1 input / later h2 [64][256]
    float* Hb   = A + TILE_E * KPAD;          // [64][256] h1
    float* Bs   = Hb + TILE_E * HDIM;         // [8][256] weight stage
    float* dirS = Bs + KT * HDIM;             // [64][3]
    int*   dstS = (int*)(dirS + TILE_E * 3);  // [64]

    const int tid = threadIdx.x;
    const int is64 = g_idx64;
    const long long e0 = (long long)blockIdx.x * TILE_E;
    const int tileE = (int)min((long long)TILE_E, (long long)E - e0);

    // ---- per-edge meta: rij, dist, dir, rbf (threads 0..63) ----
    if (tid < TILE_E) {
        int m = tid;
        if (m < tileE) {
            long long esrc = load_idx(eidx, e0 + m, is64);
            long long edst = load_idx(eidx, (long long)E + e0 + m, is64);
            dstS[m] = (int)edst;
            float rx = pos[edst * 3 + 0] - pos[esrc * 3 + 0];
            float ry = pos[edst * 3 + 1] - pos[esrc * 3 + 1];
            float rz = pos[edst * 3 + 2] - pos[esrc * 3 + 2];
            float d2 = rx * rx + ry * ry + rz * rz;
            float dist = sqrtf(d2);
            float inv = (d2 > 0.f) ? (1.0f / dist) : 0.0f;
            dirS[m * 3 + 0] = rx * inv;
            dirS[m * 3 + 1] = ry * inv;
            dirS[m * 3 + 2] = rz * inv;
#pragma unroll
            for (int j = 0; j < NRBF; ++j) {
                float t = (dist - centers[j]) / (widths[j] + 1e-8f);
                A[m * KPAD + 2 * FDIM + j] = __expf(-t * t);
            }
            for (int k = 2 * FDIM + NRBF; k < KPAD; ++k) A[m * KPAD + k] = 0.f;
        } else {
            dstS[m] = -1;
            dirS[m * 3 + 0] = dirS[m * 3 + 1] = dirS[m * 3 + 2] = 0.f;
            for (int k = 2 * FDIM; k < KPAD; ++k) A[m * KPAD + k] = 0.f;
        }
    }

    // ---- gather s[src], s[dst] rows (4 threads per edge, float4) ----
    {
        int m = tid >> 2;
        int c = tid & 3;
        bool valid = (m < tileE);
        long long esrc = 0, edst = 0;
        if (valid) {
            esrc = load_idx(eidx, e0 + m, is64);
            edst = load_idx(eidx, (long long)E + e0 + m, is64);
        }
        const float4* s4 = (const float4*)s;
        float4* Arow = (float4*)(A + m * KPAD);  // KPAD divisible by 4
        float4 z = make_float4(0.f, 0.f, 0.f, 0.f);
#pragma unroll
        for (int it = 0; it < 8; ++it) {
            int kq = c + it * 4;  // float4 index 0..31
            Arow[kq]      = valid ? s4[esrc * (FDIM / 4) + kq] : z;
            Arow[32 + kq] = valid ? s4[edst * (FDIM / 4) + kq] : z;
        }
    }
    __syncthreads();

    const int m0 = (tid >> 5) * 8;   // 8 row-groups
    const int n0 = (tid & 31) * 8;   // 32 col-groups

    float acc[8][8];

    // ---- layer 1: h1 = silu(A @ W1 + b1) ----
#pragma unroll
    for (int i = 0; i < 8; ++i)
#pragma unroll
        for (int j = 0; j < 8; ++j) acc[i][j] = 0.f;
    gemm_tile<0>(A, KPAD, KPAD, W1, nullptr, Bs, acc, m0, n0, tid);
    {
        float4 bb0 = *(const float4*)(b1 + n0);
        float4 bb1 = *(const float4*)(b1 + n0 + 4);
        float bbs[8] = {bb0.x, bb0.y, bb0.z, bb0.w, bb1.x, bb1.y, bb1.z, bb1.w};
#pragma unroll
        for (int i = 0; i < 8; ++i)
#pragma unroll
            for (int j = 0; j < 8; ++j)
                Hb[(m0 + i) * HDIM + n0 + j] = silu(acc[i][j] + bbs[j]);
    }
    __syncthreads();

    // ---- layer 2: h2 = silu(h1 @ W2 + b2), written into A region ----
#pragma unroll
    for (int i = 0; i < 8; ++i)
#pragma unroll
        for (int j = 0; j < 8; ++j) acc[i][j] = 0.f;
    gemm_tile<1>(Hb, HDIM, HDIM, W2, nullptr, Bs, acc, m0, n0, tid);
    {
        float4 bb0 = *(const float4*)(b2 + n0);
        float4 bb1 = *(const float4*)(b2 + n0 + 4);
        float bbs[8] = {bb0.x, bb0.y, bb0.z, bb0.w, bb1.x, bb1.y, bb1.z, bb1.w};
#pragma unroll
        for (int i = 0; i < 8; ++i)
#pragma unroll
            for (int j = 0; j < 8; ++j)
                A[(m0 + i) * HDIM + n0 + j] = silu(acc[i][j] + bbs[j]);
    }
    __syncthreads();

    // ---- layer 3: [ds_edge | dv_mag] = h2 @ [Ws | Wv] ----
#pragma unroll
    for (int i = 0; i < 8; ++i)
#pragma unroll
        for (int j = 0; j < 8; ++j) acc[i][j] = 0.f;
    gemm_tile<2>(A, HDIM, HDIM, Ws, Wv, Bs, acc, m0, n0, tid);

    // ---- epilogue: scatter-add into outputs ----
    if ((tid & 31) < 16) {
        // ds half: columns n0..n0+7 in [0,128)
        float4 bb0 = *(const float4*)(bs + n0);
        float4 bb1 = *(const float4*)(bs + n0 + 4);
        float bbs[8] = {bb0.x, bb0.y, bb0.z, bb0.w, bb1.x, bb1.y, bb1.z, bb1.w};
#pragma unroll
        for (int i = 0; i < 8; ++i) {
            int m = m0 + i;
            int d = dstS[m];
            if (d < 0) continue;
            float* base = out_s + (long long)d * FDIM + n0;
#pragma unroll
            for (int j = 0; j < 8; ++j) atomicAdd(base + j, acc[i][j] + bbs[j]);
        }
    } else {
        int f0 = n0 - FDIM;  // [0,128)
        float4 bb0 = *(const float4*)(bv + f0);
        float4 bb1 = *(const float4*)(bv + f0 + 4);
        float bbs[8] = {bb0.x, bb0.y, bb0.z, bb0.w, bb1.x, bb1.y, bb1.z, bb1.w};
#pragma unroll
        for (int i = 0; i < 8; ++i) {
            int m = m0 + i;
            int d = dstS[m];
            if (d < 0) continue;
            float dx = dirS[m * 3 + 0];
            float dy = dirS[m * 3 + 1];
            float dz = dirS[m * 3 + 2];
            float* base = out_v + (long long)d * 3 * FDIM + f0;
#pragma unroll
            for (int j = 0; j < 8; ++j) {
                float val = acc[i][j] + bbs[j];
                atomicAdd(base + j, dx * val);
                atomicAdd(base + FDIM + j, dy * val);
                atomicAdd(base + 2 * FDIM + j, dz * val);
            }
        }
    }
}

extern "C" void kernel_launch(void* const* d_in, const int* in_sizes, int n_in,
                              void* d_out, int out_size) {
    const float* s       = (const float*)d_in[0];
    const float* v       = (const float*)d_in[1];
    const float* pos     = (const float*)d_in[2];
    const void*  eidx    = d_in[3];
    const float* W1      = (const float*)d_in[4];
    const float* b1      = (const float*)d_in[5];
    const float* W2      = (const float*)d_in[6];
    const float* b2      = (const float*)d_in[7];
    const float* Ws      = (const float*)d_in[8];
    const float* bs      = (const float*)d_in[9];
    const float* Wv      = (const float*)d_in[10];
    const float* bv      = (const float*)d_in[11];
    const float* centers = (const float*)d_in[12];
    const float* widths  = (const float*)d_in[13];

    int N = in_sizes[0] / FDIM;
    int E = in_sizes[3] / 2;

    float* out_s = (float*)d_out;
    float* out_v = out_s + (long long)N * FDIM;

    detect_idx_kernel<<<1, 256>>>((const int*)eidx);

    int ns4 = N * FDIM / 4;
    int nv4 = N * 3 * FDIM / 4;
    init_out_kernel<<<1024, 256>>>((const float4*)s, (const float4*)v, (float4*)d_out,
                                   ns4, nv4);

    size_t smembytes = (size_t)(TILE_E * KPAD + TILE_E * HDIM + KT * HDIM + TILE_E * 3) *
                           sizeof(float) +
                       TILE_E * sizeof(int);
    cudaFuncSetAttribute(painn_edge_kernel, cudaFuncAttributeMaxDynamicSharedMemorySize,
                         (int)smembytes);

    int grid = (E + TILE_E - 1) / TILE_E;
    painn_edge_kernel<<<grid, NTHREADS, smembytes>>>(
        s, pos, eidx, W1, b1, W2, b2, Ws, bs, Wv, bv, centers, widths, out_s, out_v, E, N);
}

// round 7
// speedup vs baseline: 3.6409x; 3.6409x over previous
#include <cuda_runtime.h>
#include <cuda_bf16.h>
#include <cstdint>
#include <math.h>

// PaiNN interaction — fused mma.sync (HMMA) bf16 tensor-core kernel.
// No tcgen05/TMEM/TMA: baseline PTX, compiles for compute_103 and sm_103a.
//
// Inputs (metadata order):
// 0 s [N,128] f32, 1 v [N,3,128] f32, 2 pos [N,3] f32, 3 edge_index [2,E] int32-or-int64,
// 4 W1 [276,256], 5 b1, 6 W2 [256,256], 7 b2, 8 Ws [256,128], 9 bs,
// 10 Wv [256,128], 11 bv, 12 centers[20], 13 widths[20]
// Output: concat(s_out [N,128], v_out [N,3,128]) f32.

#define FDIM 128
#define NRBF 20
#define IN_DIM 276
#define K1 320              // layer-1 K padded
#define K23 256
#define TILE_E 64
#define NTHREADS 256

#define ASTRIDE 324         // bf16 elems per A row (pairs: 162)
#define APAIRS 162
#define A_BYTES (TILE_E * ASTRIDE * 2)          // 41472
#define BSTRIDE 72          // bf16 elems per B row (36 pairs, 144B, 16B-mult)
#define B_BYTES (256 * BSTRIDE * 2)             // 36864
#define DST_OFF (A_BYTES + B_BYTES)             // int dstS[64]
#define DIR_OFF (DST_OFF + 256)                 // float dirS[64*3]
#define SMEM_TOTAL (DIR_OFF + 768)

// ---------------- device globals ----------------
__device__ __align__(16) __nv_bfloat16 g_W1T[256 * K1];    // [n][k], k>=276 zero
__device__ __align__(16) __nv_bfloat16 g_W2T[256 * K23];
__device__ __align__(16) __nv_bfloat16 g_WsvT[256 * K23];  // n<128 Ws, n>=128 Wv
__device__ int g_idx64;

// ---------------- helpers ----------------
__device__ __forceinline__ uint32_t packbf(float a, float b) {
    __nv_bfloat162 h = __floats2bfloat162_rn(a, b);
    return *reinterpret_cast<uint32_t*>(&h);
}
__device__ __forceinline__ float silu(float x) { return x / (1.0f + __expf(-x)); }

__device__ __forceinline__ void mma16816(float c[4], uint32_t a0, uint32_t a1, uint32_t a2,
                                         uint32_t a3, uint32_t b0, uint32_t b1) {
    asm volatile(
        "mma.sync.aligned.m16n8k16.row.col.f32.bf16.bf16.f32 "
        "{%0,%1,%2,%3}, {%4,%5,%6,%7}, {%8,%9}, {%0,%1,%2,%3};"
        : "+f"(c[0]), "+f"(c[1]), "+f"(c[2]), "+f"(c[3])
        : "r"(a0), "r"(a1), "r"(a2), "r"(a3), "r"(b0), "r"(b1));
}

__device__ __forceinline__ void red2(float* p, float a, float b) {
    asm volatile("red.global.add.v2.f32 [%0], {%1, %2};" :: "l"(p), "f"(a), "f"(b) : "memory");
}

__device__ __forceinline__ long long load_idx(const void* p, long long i, int is64) {
    if (is64) return ((const long long*)p)[i];
    return (long long)((const int*)p)[i];
}

// ---------------- small helper kernels ----------------
__global__ void detect_idx_kernel(const int* __restrict__ idx32) {
    __shared__ int nz;
    if (threadIdx.x == 0) nz = 0;
    __syncthreads();
    int v = idx32[2 * threadIdx.x + 1];
    if (v != 0) atomicOr(&nz, 1);
    __syncthreads();
    if (threadIdx.x == 0) g_idx64 = (nz == 0) ? 1 : 0;
}

__global__ void init_out_kernel(const float4* __restrict__ s, const float4* __restrict__ v,
                                float4* __restrict__ out, int ns4, int nv4) {
    int stride = gridDim.x * blockDim.x;
    for (int i = blockIdx.x * blockDim.x + threadIdx.x; i < ns4; i += stride) out[i] = s[i];
    for (int i = blockIdx.x * blockDim.x + threadIdx.x; i < nv4; i += stride)
        out[ns4 + i] = v[i];
}

__global__ void prep_weights(const float* __restrict__ W1, const float* __restrict__ W2,
                             const float* __restrict__ Ws, const float* __restrict__ Wv) {
    const int t1 = 256 * K1;
    const int t2 = t1 + 256 * K23;
    const int t3 = t2 + 256 * K23;
    int stride = gridDim.x * blockDim.x;
    for (int idx = blockIdx.x * blockDim.x + threadIdx.x; idx < t3; idx += stride) {
        if (idx < t1) {
            int n = idx / K1, k = idx % K1;
            g_W1T[idx] = __float2bfloat16((k < IN_DIM) ? W1[k * 256 + n] : 0.0f);
        } else if (idx < t2) {
            int r = idx - t1;
            int n = r / K23, k = r % K23;
            g_W2T[r] = __float2bfloat16(W2[k * 256 + n]);
        } else {
            int r = idx - t2;
            int n = r / K23, k = r % K23;
            float val = (n < FDIM) ? Ws[k * FDIM + n] : Wv[k * FDIM + (n - FDIM)];
            g_WsvT[r] = __float2bfloat16(val);
        }
    }
}

// ---------------- main fused kernel ----------------
__global__ __launch_bounds__(NTHREADS, 2)
void painn_mma_kernel(const float* __restrict__ s, const float* __restrict__ pos,
                      const void* __restrict__ eidx,
                      const float* __restrict__ b1, const float* __restrict__ b2,
                      const float* __restrict__ bs, const float* __restrict__ bv,
                      const float* __restrict__ centers, const float* __restrict__ widths,
                      float* __restrict__ out_s, float* __restrict__ out_v, int E) {
    extern __shared__ char smem[];
    uint32_t* A32 = (uint32_t*)smem;                    // [64][162] bf16 pairs
    uint32_t* B32 = (uint32_t*)(smem + A_BYTES);        // [256][36] bf16 pairs
    int* dstS = (int*)(smem + DST_OFF);
    float* dirS = (float*)(smem + DIR_OFF);

    const int tid = threadIdx.x;
    const int wid = tid >> 5;
    const int lane = tid & 31;
    const int g = lane >> 2;      // group 0..7
    const int tig = lane & 3;     // thread-in-group
    const int warp_m = wid & 3;   // 0..3
    const int warp_n = wid >> 2;  // 0..1
    const int m0 = warp_m * 16;
    const int n0 = warp_n * 128;

    const int is64 = g_idx64;
    const long long e0 = (long long)blockIdx.x * TILE_E;

    // ---- build A + meta: 4 threads per edge ----
    {
        const int m = tid >> 2;
        const int c = tid & 3;
        const bool valid = (e0 + m) < (long long)E;
        if (valid) {
            long long srcI = load_idx(eidx, e0 + m, is64);
            long long dstI = load_idx(eidx, (long long)E + e0 + m, is64);
            long long node = (c < 2) ? srcI : dstI;
            const float4* rp = (const float4*)(s + node * FDIM + (c & 1) * 64);
            uint32_t* Arow = A32 + m * APAIRS + c * 32;
#pragma unroll
            for (int q = 0; q < 16; ++q) {
                float4 t = __ldg(rp + q);
                Arow[2 * q]     = packbf(t.x, t.y);
                Arow[2 * q + 1] = packbf(t.z, t.w);
            }
            if (c == 0) {
                float rx = pos[dstI * 3 + 0] - pos[srcI * 3 + 0];
                float ry = pos[dstI * 3 + 1] - pos[srcI * 3 + 1];
                float rz = pos[dstI * 3 + 2] - pos[srcI * 3 + 2];
                float d2 = rx * rx + ry * ry + rz * rz;
                float dist = sqrtf(d2);
                float inv = (d2 > 0.f) ? (1.0f / dist) : 0.0f;
                dstS[m] = (int)dstI;
                dirS[m * 3 + 0] = rx * inv;
                dirS[m * 3 + 1] = ry * inv;
                dirS[m * 3 + 2] = rz * inv;
            } else if (c == 3) {
                float rx = pos[dstI * 3 + 0] - pos[srcI * 3 + 0];
                float ry = pos[dstI * 3 + 1] - pos[srcI * 3 + 1];
                float rz = pos[dstI * 3 + 2] - pos[srcI * 3 + 2];
                float dist = sqrtf(rx * rx + ry * ry + rz * rz);
                uint32_t* Ar = A32 + m * APAIRS + 128;   // cols 256..319
#pragma unroll
                for (int j = 0; j < 32; ++j) {
                    float f0 = 0.f, f1 = 0.f;
                    int j0 = 2 * j, j1 = 2 * j + 1;
                    if (j0 < NRBF) {
                        float t = (dist - __ldg(centers + j0)) / (__ldg(widths + j0) + 1e-8f);
                        f0 = __expf(-t * t);
                    }
                    if (j1 < NRBF) {
                        float t = (dist - __ldg(centers + j1)) / (__ldg(widths + j1) + 1e-8f);
                        f1 = __expf(-t * t);
                    }
                    Ar[j] = packbf(f0, f1);
                }
            }
        } else {
            uint32_t* Arow = A32 + m * APAIRS + c * 32;
#pragma unroll
            for (int q = 0; q < 32; ++q) Arow[q] = 0;
            if (c == 0) dstS[m] = -1;
            if (c == 3) {
                uint32_t* Ar = A32 + m * APAIRS + 128;
#pragma unroll
                for (int j = 0; j < 32; ++j) Ar[j] = 0;
            }
        }
    }

    float acc[16][4];

#pragma unroll 1
    for (int L = 0; L < 3; ++L) {
        const __nv_bfloat16* wsrc = (L == 0) ? g_W1T : ((L == 1) ? g_W2T : g_WsvT);
        const int Kl = (L == 0) ? K1 : K23;

#pragma unroll
        for (int t = 0; t < 16; ++t)
#pragma unroll
            for (int i = 0; i < 4; ++i) acc[t][i] = 0.f;

#pragma unroll 1
        for (int c0 = 0; c0 < Kl; c0 += 64) {
            __syncthreads();  // prior compute done before B overwrite / A reads ordered
            // stage B chunk: thread t = row n, 8 uint4 (128B) each
            {
                const uint4* src = (const uint4*)(wsrc + (size_t)tid * Kl + c0);
                uint4* dst = (uint4*)(smem + A_BYTES + tid * (BSTRIDE * 2));
#pragma unroll
                for (int i = 0; i < 8; ++i) dst[i] = __ldg(src + i);
            }
            __syncthreads();
            // compute 4 k-steps of 16
            const int rowA0 = (m0 + g) * APAIRS;
            const int rowA1 = rowA0 + 8 * APAIRS;
#pragma unroll
            for (int ks = 0; ks < 4; ++ks) {
                const int kp = (c0 >> 1) + ks * 8;   // global pair base for A
                const int kpb = ks * 8;              // chunk-local pair base for B
                uint32_t a0 = A32[rowA0 + kp + tig];
                uint32_t a1 = A32[rowA1 + kp + tig];
                uint32_t a2 = A32[rowA0 + kp + 4 + tig];
                uint32_t a3 = A32[rowA1 + kp + 4 + tig];
#pragma unroll
                for (int t = 0; t < 16; ++t) {
                    const int n = n0 + t * 8 + g;
                    uint32_t b0 = B32[n * 36 + kpb + tig];
                    uint32_t b1 = B32[n * 36 + kpb + 4 + tig];
                    mma16816(acc[t], a0, a1, a2, a3, b0, b1);
                }
            }
        }
        __syncthreads();  // all compute done; A free to overwrite

        if (L < 2) {
            const float* bias = (L == 0) ? b1 : b2;
#pragma unroll
            for (int t = 0; t < 16; ++t) {
                const int col = n0 + t * 8 + tig * 2;
                float bb0 = __ldg(bias + col);
                float bb1 = __ldg(bias + col + 1);
                const int pr = col >> 1;
                A32[(m0 + g) * APAIRS + pr] =
                    packbf(silu(acc[t][0] + bb0), silu(acc[t][1] + bb1));
                A32[(m0 + g + 8) * APAIRS + pr] =
                    packbf(silu(acc[t][2] + bb0), silu(acc[t][3] + bb1));
            }
            // next layer's first chunk-loop __syncthreads orders these writes
        } else {
            // final scatter
            const int r0 = m0 + g, r1 = m0 + g + 8;
            const int d0 = dstS[r0], d1 = dstS[r1];
            if (warp_n == 0) {
#pragma unroll
                for (int t = 0; t < 16; ++t) {
                    const int col = t * 8 + tig * 2;
                    float bb0 = __ldg(bs + col), bb1 = __ldg(bs + col + 1);
                    if (d0 >= 0)
                        red2(out_s + (long long)d0 * FDIM + col, acc[t][0] + bb0,
                             acc[t][1] + bb1);
                    if (d1 >= 0)
                        red2(out_s + (long long)d1 * FDIM + col, acc[t][2] + bb0,
                             acc[t][3] + bb1);
                }
            } else {
                float dx0 = dirS[r0 * 3], dy0 = dirS[r0 * 3 + 1], dz0 = dirS[r0 * 3 + 2];
                float dx1 = dirS[r1 * 3], dy1 = dirS[r1 * 3 + 1], dz1 = dirS[r1 * 3 + 2];
#pragma unroll
                for (int t = 0; t < 16; ++t) {
                    const int col = t * 8 + tig * 2;
                    float bb0 = __ldg(bv + col), bb1 = __ldg(bv + col + 1);
                    if (d0 >= 0) {
                        float v0 = acc[t][0] + bb0, v1 = acc[t][1] + bb1;
                        float* vb = out_v + (long long)d0 * 3 * FDIM + col;
                        red2(vb, dx0 * v0, dx0 * v1);
                        red2(vb + FDIM, dy0 * v0, dy0 * v1);
                        red2(vb + 2 * FDIM, dz0 * v0, dz0 * v1);
                    }
                    if (d1 >= 0) {
                        float v0 = acc[t][2] + bb0, v1 = acc[t][3] + bb1;
                        float* vb = out_v + (long long)d1 * 3 * FDIM + col;
                        red2(vb, dx1 * v0, dx1 * v1);
                        red2(vb + FDIM, dy1 * v0, dy1 * v1);
                        red2(vb + 2 * FDIM, dz1 * v0, dz1 * v1);
                    }
                }
            }
        }
    }
}

// ---------------- launcher ----------------
extern "C" void kernel_launch(void* const* d_in, const int* in_sizes, int n_in,
                              void* d_out, int out_size) {
    const float* s       = (const float*)d_in[0];
    const float* v       = (const float*)d_in[1];
    const float* pos     = (const float*)d_in[2];
    const void*  eidx    = d_in[3];
    const float* W1      = (const float*)d_in[4];
    const float* b1      = (const float*)d_in[5];
    const float* W2      = (const float*)d_in[6];
    const float* b2      = (const float*)d_in[7];
    const float* Ws      = (const float*)d_in[8];
    const float* bs      = (const float*)d_in[9];
    const float* Wv      = (const float*)d_in[10];
    const float* bv      = (const float*)d_in[11];
    const float* centers = (const float*)d_in[12];
    const float* widths  = (const float*)d_in[13];

    int N = in_sizes[0] / FDIM;
    int E = in_sizes[3] / 2;

    float* out_s = (float*)d_out;
    float* out_v = out_s + (long long)N * FDIM;

    detect_idx_kernel<<<1, 256>>>((const int*)eidx);

    int ns4 = N * FDIM / 4;
    int nv4 = N * 3 * FDIM / 4;
    init_out_kernel<<<1024, 256>>>((const float4*)s, (const float4*)v, (float4*)d_out, ns4, nv4);

    prep_weights<<<256, 256>>>(W1, W2, Ws, Wv);

    cudaFuncSetAttribute(painn_mma_kernel, cudaFuncAttributeMaxDynamicSharedMemorySize,
                         SMEM_TOTAL);

    int grid = (E + TILE_E - 1) / TILE_E;
    painn_mma_kernel<<<grid, NTHREADS, SMEM_TOTAL>>>(s, pos, eidx, b1, b2, bs, bv, centers,
                                                     widths, out_s, out_v, E);
}

// round 8
// speedup vs baseline: 4.1494x; 1.1397x over previous
#include <cuda_runtime.h>
#include <cuda_bf16.h>
#include <cstdint>
#include <math.h>

// PaiNN interaction — fused mma.sync (HMMA) bf16 kernel, ldmatrix edition.
// Round-7 profile: L1=82.7% (LDS-bound), tensor=18%. This round: ldmatrix.x4
// fragments, 2Mx4N warp tiling (halves B traffic), bank-exact padding, cp.async.
//
// Inputs (metadata order):
// 0 s [N,128] f32, 1 v [N,3,128] f32, 2 pos [N,3] f32, 3 edge_index [2,E] i32/i64,
// 4 W1 [276,256], 5 b1, 6 W2 [256,256], 7 b2, 8 Ws [256,128], 9 bs,
// 10 Wv [256,128], 11 bv, 12 centers[20], 13 widths[20]
// Output: concat(s_out [N,128], v_out [N,3,128]) f32.

#define FDIM 128
#define NRBF 20
#define IN_DIM 276
#define K1 320
#define K23 256
#define TILE_E 64
#define NTHREADS 256

#define ASTRIDE 328         // bf16 elems per A row; 164 u32 = 4 mod 32 (bank-perfect)
#define APAIRS 164
#define A_BYTES (TILE_E * ASTRIDE * 2)          // 41984
#define BSTRIDE 72          // bf16 per B row; 36 u32 = 4 mod 32 (bank-perfect)
#define B_BYTES (256 * BSTRIDE * 2)             // 36864
#define DST_OFF (A_BYTES + B_BYTES)
#define DIR_OFF (DST_OFF + 256)
#define SMEM_TOTAL (DIR_OFF + 768)

// ---------------- device globals ----------------
__device__ __align__(16) __nv_bfloat16 g_W1T[256 * K1];    // [n][k], k>=276 zero
__device__ __align__(16) __nv_bfloat16 g_W2T[256 * K23];
__device__ __align__(16) __nv_bfloat16 g_WsvT[256 * K23];  // n<128 Ws, n>=128 Wv
__device__ int g_idx64;

// ---------------- helpers ----------------
__device__ __forceinline__ uint32_t smem_u32(const void* p) {
    uint32_t a;
    asm("{ .reg .u64 t; cvta.to.shared.u64 t, %1; cvt.u32.u64 %0, t; }" : "=r"(a) : "l"(p));
    return a;
}
__device__ __forceinline__ uint32_t packbf(float a, float b) {
    __nv_bfloat162 h = __floats2bfloat162_rn(a, b);
    return *reinterpret_cast<uint32_t*>(&h);
}
__device__ __forceinline__ float silu(float x) { return x / (1.0f + __expf(-x)); }

__device__ __forceinline__ void mma16816(float c[4], uint32_t a0, uint32_t a1, uint32_t a2,
                                         uint32_t a3, uint32_t b0, uint32_t b1) {
    asm volatile(
        "mma.sync.aligned.m16n8k16.row.col.f32.bf16.bf16.f32 "
        "{%0,%1,%2,%3}, {%4,%5,%6,%7}, {%8,%9}, {%0,%1,%2,%3};"
        : "+f"(c[0]), "+f"(c[1]), "+f"(c[2]), "+f"(c[3])
        : "r"(a0), "r"(a1), "r"(a2), "r"(a3), "r"(b0), "r"(b1));
}

__device__ __forceinline__ void ldm_x4(uint32_t r[4], uint32_t addr) {
    asm volatile("ldmatrix.sync.aligned.m8n8.x4.shared.b16 {%0,%1,%2,%3}, [%4];"
                 : "=r"(r[0]), "=r"(r[1]), "=r"(r[2]), "=r"(r[3]) : "r"(addr));
}

__device__ __forceinline__ void cpasync16(uint32_t dst, const void* src) {
    asm volatile("cp.async.cg.shared.global [%0], [%1], 16;" :: "r"(dst), "l"(src)
                 : "memory");
}

__device__ __forceinline__ void red2(float* p, float a, float b) {
    asm volatile("red.global.add.v2.f32 [%0], {%1, %2};" :: "l"(p), "f"(a), "f"(b) : "memory");
}

__device__ __forceinline__ long long load_idx(const void* p, long long i, int is64) {
    if (is64) return ((const long long*)p)[i];
    return (long long)((const int*)p)[i];
}

// ---------------- small helper kernels ----------------
__global__ void detect_idx_kernel(const int* __restrict__ idx32) {
    __shared__ int nz;
    if (threadIdx.x == 0) nz = 0;
    __syncthreads();
    int v = idx32[2 * threadIdx.x + 1];
    if (v != 0) atomicOr(&nz, 1);
    __syncthreads();
    if (threadIdx.x == 0) g_idx64 = (nz == 0) ? 1 : 0;
}

__global__ void init_out_kernel(const float4* __restrict__ s, const float4* __restrict__ v,
                                float4* __restrict__ out, int ns4, int nv4) {
    int stride = gridDim.x * blockDim.x;
    for (int i = blockIdx.x * blockDim.x + threadIdx.x; i < ns4; i += stride) out[i] = s[i];
    for (int i = blockIdx.x * blockDim.x + threadIdx.x; i < nv4; i += stride)
        out[ns4 + i] = v[i];
}

__global__ void prep_weights(const float* __restrict__ W1, const float* __restrict__ W2,
                             const float* __restrict__ Ws, const float* __restrict__ Wv) {
    const int t1 = 256 * K1;
    const int t2 = t1 + 256 * K23;
    const int t3 = t2 + 256 * K23;
    int stride = gridDim.x * blockDim.x;
    for (int idx = blockIdx.x * blockDim.x + threadIdx.x; idx < t3; idx += stride) {
        if (idx < t1) {
            int n = idx / K1, k = idx % K1;
            g_W1T[idx] = __float2bfloat16((k < IN_DIM) ? W1[k * 256 + n] : 0.0f);
        } else if (idx < t2) {
            int r = idx - t1;
            int n = r / K23, k = r % K23;
            g_W2T[r] = __float2bfloat16(W2[k * 256 + n]);
        } else {
            int r = idx - t2;
            int n = r / K23, k = r % K23;
            float val = (n < FDIM) ? Ws[k * FDIM + n] : Wv[k * FDIM + (n - FDIM)];
            g_WsvT[r] = __float2bfloat16(val);
        }
    }
}

// ---------------- main fused kernel ----------------
__global__ __launch_bounds__(NTHREADS, 2)
void painn_mma_kernel(const float* __restrict__ s, const float* __restrict__ pos,
                      const void* __restrict__ eidx,
                      const float* __restrict__ b1, const float* __restrict__ b2,
                      const float* __restrict__ bs, const float* __restrict__ bv,
                      const float* __restrict__ centers, const float* __restrict__ widths,
                      float* __restrict__ out_s, float* __restrict__ out_v, int E) {
    extern __shared__ char smem[];
    uint32_t* A32 = (uint32_t*)smem;                    // [64][164] bf16 pairs
    int* dstS = (int*)(smem + DST_OFF);
    float* dirS = (float*)(smem + DIR_OFF);
    const uint32_t Abase = smem_u32(smem);
    const uint32_t Bbase = Abase + A_BYTES;

    const int tid = threadIdx.x;
    const int wid = tid >> 5;
    const int lane = tid & 31;
    const int g = lane >> 2;
    const int tig = lane & 3;
    const int quad = lane >> 3;     // 0..3 (ldmatrix tile select)
    const int rowin = lane & 7;     // row within 8-row tile
    const int warp_m = wid & 1;     // 2 M-warps
    const int warp_n = wid >> 1;    // 4 N-warps
    const int m0 = warp_m * 32;
    const int n0 = warp_n * 64;

    const int is64 = g_idx64;
    const long long e0 = (long long)blockIdx.x * TILE_E;

    // ---- build A + meta: 4 threads per edge ----
    {
        const int m = tid >> 2;
        const int c = tid & 3;
        const bool valid = (e0 + m) < (long long)E;
        if (valid) {
            long long srcI = load_idx(eidx, e0 + m, is64);
            long long dstI = load_idx(eidx, (long long)E + e0 + m, is64);
            long long node = (c < 2) ? srcI : dstI;
            const float4* rp = (const float4*)(s + node * FDIM + (c & 1) * 64);
            uint32_t* Arow = A32 + m * APAIRS + c * 32;
#pragma unroll
            for (int q = 0; q < 16; ++q) {
                float4 t = __ldg(rp + q);
                Arow[2 * q]     = packbf(t.x, t.y);
                Arow[2 * q + 1] = packbf(t.z, t.w);
            }
            if (c == 0) {
                float rx = pos[dstI * 3 + 0] - pos[srcI * 3 + 0];
                float ry = pos[dstI * 3 + 1] - pos[srcI * 3 + 1];
                float rz = pos[dstI * 3 + 2] - pos[srcI * 3 + 2];
                float d2 = rx * rx + ry * ry + rz * rz;
                float dist = sqrtf(d2);
                float inv = (d2 > 0.f) ? (1.0f / dist) : 0.0f;
                dstS[m] = (int)dstI;
                dirS[m * 3 + 0] = rx * inv;
                dirS[m * 3 + 1] = ry * inv;
                dirS[m * 3 + 2] = rz * inv;
            } else if (c == 3) {
                float rx = pos[dstI * 3 + 0] - pos[srcI * 3 + 0];
                float ry = pos[dstI * 3 + 1] - pos[srcI * 3 + 1];
                float rz = pos[dstI * 3 + 2] - pos[srcI * 3 + 2];
                float dist = sqrtf(rx * rx + ry * ry + rz * rz);
                uint32_t* Ar = A32 + m * APAIRS + 128;   // cols 256..319
#pragma unroll
                for (int j = 0; j < 32; ++j) {
                    float f0 = 0.f, f1 = 0.f;
                    int j0 = 2 * j, j1 = 2 * j + 1;
                    if (j0 < NRBF) {
                        float t = (dist - __ldg(centers + j0)) / (__ldg(widths + j0) + 1e-8f);
                        f0 = __expf(-t * t);
                    }
                    if (j1 < NRBF) {
                        float t = (dist - __ldg(centers + j1)) / (__ldg(widths + j1) + 1e-8f);
                        f1 = __expf(-t * t);
                    }
                    Ar[j] = packbf(f0, f1);
                }
                // zero pad pairs 160..163
                A32[m * APAIRS + 160] = 0; A32[m * APAIRS + 161] = 0;
                A32[m * APAIRS + 162] = 0; A32[m * APAIRS + 163] = 0;
            }
        } else {
            uint32_t* Arow = A32 + m * APAIRS + c * 32;
#pragma unroll
            for (int q = 0; q < 32; ++q) Arow[q] = 0;
            if (c == 0) dstS[m] = -1;
            if (c == 3) {
                uint32_t* Ar = A32 + m * APAIRS + 128;
#pragma unroll
                for (int j = 0; j < 36; ++j) Ar[j] = 0;
            }
        }
    }

    float acc[2][8][4];

#pragma unroll 1
    for (int L = 0; L < 3; ++L) {
        const __nv_bfloat16* wsrc = (L == 0) ? g_W1T : ((L == 1) ? g_W2T : g_WsvT);
        const int Kl = (L == 0) ? K1 : K23;

#pragma unroll
        for (int mb = 0; mb < 2; ++mb)
#pragma unroll
            for (int t = 0; t < 8; ++t)
#pragma unroll
                for (int i = 0; i < 4; ++i) acc[mb][t][i] = 0.f;

#pragma unroll 1
        for (int c0 = 0; c0 < Kl; c0 += 64) {
            __syncthreads();  // prior compute done before B overwrite
            // stage B chunk via cp.async: thread = row n, 128B
            {
                const char* src = (const char*)(wsrc + (size_t)tid * Kl + c0);
                uint32_t dst = Bbase + tid * (BSTRIDE * 2);
#pragma unroll
                for (int i = 0; i < 8; ++i) cpasync16(dst + i * 16, src + i * 16);
                asm volatile("cp.async.commit_group;" ::: "memory");
                asm volatile("cp.async.wait_group 0;" ::: "memory");
            }
            __syncthreads();

#pragma unroll
            for (int ks = 0; ks < 4; ++ks) {
                const int KPa = (c0 >> 1) + ks * 8;  // A global pair base
                const int KB = ks * 8;               // B chunk-local pair base
                uint32_t afr[2][4];
#pragma unroll
                for (int mb = 0; mb < 2; ++mb) {
                    int row = m0 + mb * 16 + (quad & 1) * 8 + rowin;
                    int kp = KPa + (quad >> 1) * 4;
                    ldm_x4(afr[mb], Abase + (uint32_t)(row * APAIRS + kp) * 4u);
                }
#pragma unroll
                for (int tp = 0; tp < 4; ++tp) {
                    uint32_t bfr[4];
                    int n = n0 + tp * 16 + (quad >> 1) * 8 + rowin;
                    int kp = KB + (quad & 1) * 4;
                    ldm_x4(bfr, Bbase + (uint32_t)(n * 36 + kp) * 4u);
#pragma unroll
                    for (int mb = 0; mb < 2; ++mb) {
                        mma16816(acc[mb][2 * tp], afr[mb][0], afr[mb][1], afr[mb][2],
                                 afr[mb][3], bfr[0], bfr[1]);
                        mma16816(acc[mb][2 * tp + 1], afr[mb][0], afr[mb][1], afr[mb][2],
                                 afr[mb][3], bfr[2], bfr[3]);
                    }
                }
            }
        }
        __syncthreads();  // compute done; A free to overwrite

        if (L < 2) {
            const float* bias = (L == 0) ? b1 : b2;
#pragma unroll
            for (int mb = 0; mb < 2; ++mb) {
                const int r0 = m0 + mb * 16 + g;
#pragma unroll
                for (int t = 0; t < 8; ++t) {
                    const int col = n0 + t * 8 + tig * 2;
                    float bb0 = __ldg(bias + col);
                    float bb1 = __ldg(bias + col + 1);
                    const int pr = col >> 1;
                    A32[r0 * APAIRS + pr] =
                        packbf(silu(acc[mb][t][0] + bb0), silu(acc[mb][t][1] + bb1));
                    A32[(r0 + 8) * APAIRS + pr] =
                        packbf(silu(acc[mb][t][2] + bb0), silu(acc[mb][t][3] + bb1));
                }
            }
        } else {
            // final scatter: warp_n 0,1 -> ds (cols 0..127); warp_n 2,3 -> dv
#pragma unroll
            for (int mb = 0; mb < 2; ++mb) {
                const int r0 = m0 + mb * 16 + g, r1 = r0 + 8;
                const int d0 = dstS[r0], d1 = dstS[r1];
                if (n0 < 128) {
#pragma unroll
                    for (int t = 0; t < 8; ++t) {
                        const int col = n0 + t * 8 + tig * 2;
                        float bb0 = __ldg(bs + col), bb1 = __ldg(bs + col + 1);
                        if (d0 >= 0)
                            red2(out_s + (long long)d0 * FDIM + col, acc[mb][t][0] + bb0,
                                 acc[mb][t][1] + bb1);
                        if (d1 >= 0)
                            red2(out_s + (long long)d1 * FDIM + col, acc[mb][t][2] + bb0,
                                 acc[mb][t][3] + bb1);
                    }
                } else {
                    float dx0 = dirS[r0 * 3], dy0 = dirS[r0 * 3 + 1], dz0 = dirS[r0 * 3 + 2];
                    float dx1 = dirS[r1 * 3], dy1 = dirS[r1 * 3 + 1], dz1 = dirS[r1 * 3 + 2];
#pragma unroll
                    for (int t = 0; t < 8; ++t) {
                        const int col = n0 - 128 + t * 8 + tig * 2;
                        float bb0 = __ldg(bv + col), bb1 = __ldg(bv + col + 1);
                        if (d0 >= 0) {
                            float v0 = acc[mb][t][0] + bb0, v1 = acc[mb][t][1] + bb1;
                            float* vb = out_v + (long long)d0 * 3 * FDIM + col;
                            red2(vb, dx0 * v0, dx0 * v1);
                            red2(vb + FDIM, dy0 * v0, dy0 * v1);
                            red2(vb + 2 * FDIM, dz0 * v0, dz0 * v1);
                        }
                        if (d1 >= 0) {
                            float v0 = acc[mb][t][2] + bb0, v1 = acc[mb][t][3] + bb1;
                            float* vb = out_v + (long long)d1 * 3 * FDIM + col;
                            red2(vb, dx1 * v0, dx1 * v1);
                            red2(vb + FDIM, dy1 * v0, dy1 * v1);
                            red2(vb + 2 * FDIM, dz1 * v0, dz1 * v1);
                        }
                    }
                }
            }
        }
    }
}

// ---------------- launcher ----------------
extern "C" void kernel_launch(void* const* d_in, const int* in_sizes, int n_in,
                              void* d_out, int out_size) {
    const float* s       = (const float*)d_in[0];
    const float* v       = (const float*)d_in[1];
    const float* pos     = (const float*)d_in[2];
    const void*  eidx    = d_in[3];
    const float* W1      = (const float*)d_in[4];
    const float* b1      = (const float*)d_in[5];
    const float* W2      = (const float*)d_in[6];
    const float* b2      = (const float*)d_in[7];
    const float* Ws      = (const float*)d_in[8];
    const float* bs      = (const float*)d_in[9];
    const float* Wv      = (const float*)d_in[10];
    const float* bv      = (const float*)d_in[11];
    const float* centers = (const float*)d_in[12];
    const float* widths  = (const float*)d_in[13];

    int N = in_sizes[0] / FDIM;
    int E = in_sizes[3] / 2;

    float* out_s = (float*)d_out;
    float* out_v = out_s + (long long)N * FDIM;

    detect_idx_kernel<<<1, 256>>>((const int*)eidx);

    int ns4 = N * FDIM / 4;
    int nv4 = N * 3 * FDIM / 4;
    init_out_kernel<<<1024, 256>>>((const float4*)s, (const float4*)v, (float4*)d_out, ns4, nv4);

    prep_weights<<<256, 256>>>(W1, W2, Ws, Wv);

    cudaFuncSetAttribute(painn_mma_kernel, cudaFuncAttributeMaxDynamicSharedMemorySize,
                         SMEM_TOTAL);

    int grid = (E + TILE_E - 1) / TILE_E;
    painn_mma_kernel<<<grid, NTHREADS, SMEM_TOTAL>>>(s, pos, eidx, b1, b2, bs, bv, centers,
                                                     widths, out_s, out_v, E);
}

// round 9
// speedup vs baseline: 4.6714x; 1.1258x over previous
#include <cuda_runtime.h>
#include <cuda_bf16.h>
#include <cstdint>
#include <math.h>

// PaiNN interaction — fused HMMA bf16 kernel, round 9.
// R8 profile: L1 41.5%, L2 42%, tensor 20.7%, issue 16.4% -> latency + B-traffic bound.
// This round: TILE_E=128 w/ 512 threads (halves B traffic/edge), double-buffered
// cp.async weight pipeline (hides L2 latency behind MMA).
//
// Inputs: 0 s [N,128] f32, 1 v [N,3,128] f32, 2 pos [N,3] f32, 3 edge_index [2,E],
// 4 W1 [276,256], 5 b1, 6 W2, 7 b2, 8 Ws, 9 bs, 10 Wv, 11 bv, 12 centers, 13 widths
// Output: concat(s_out [N,128], v_out [N,3,128]) f32.

#define FDIM 128
#define NRBF 20
#define IN_DIM 276
#define K1 320
#define K23 256
#define TILE_E 128
#define NTHREADS 512
#define NCHUNK_TOT 13        // 5 + 4 + 4

#define APAIRS 164           // u32 per A row (328 bf16); 164 % 32 == 4 (bank-perfect)
#define A_BYTES (TILE_E * APAIRS * 4)            // 83968
#define BROW_BYTES 144       // 72 bf16 per B row (36 u32); 36 % 32 == 4
#define B_BYTES (256 * BROW_BYTES)               // 36864
#define B0_OFF A_BYTES
#define B1_OFF (A_BYTES + B_BYTES)
#define DST_OFF (A_BYTES + 2 * B_BYTES)
#define DIR_OFF (DST_OFF + 512)
#define SMEM_TOTAL (DIR_OFF + 1536)

// ---------------- device globals ----------------
__device__ __align__(16) __nv_bfloat16 g_W1T[256 * K1];    // [n][k], k>=276 zero
__device__ __align__(16) __nv_bfloat16 g_W2T[256 * K23];
__device__ __align__(16) __nv_bfloat16 g_WsvT[256 * K23];  // n<128 Ws, n>=128 Wv
__device__ int g_idx64;

// ---------------- helpers ----------------
__device__ __forceinline__ uint32_t smem_u32(const void* p) {
    uint32_t a;
    asm("{ .reg .u64 t; cvta.to.shared.u64 t, %1; cvt.u32.u64 %0, t; }" : "=r"(a) : "l"(p));
    return a;
}
__device__ __forceinline__ uint32_t packbf(float a, float b) {
    __nv_bfloat162 h = __floats2bfloat162_rn(a, b);
    return *reinterpret_cast<uint32_t*>(&h);
}
__device__ __forceinline__ float silu(float x) { return x / (1.0f + __expf(-x)); }

__device__ __forceinline__ void mma16816(float c[4], uint32_t a0, uint32_t a1, uint32_t a2,
                                         uint32_t a3, uint32_t b0, uint32_t b1) {
    asm volatile(
        "mma.sync.aligned.m16n8k16.row.col.f32.bf16.bf16.f32 "
        "{%0,%1,%2,%3}, {%4,%5,%6,%7}, {%8,%9}, {%0,%1,%2,%3};"
        : "+f"(c[0]), "+f"(c[1]), "+f"(c[2]), "+f"(c[3])
        : "r"(a0), "r"(a1), "r"(a2), "r"(a3), "r"(b0), "r"(b1));
}

__device__ __forceinline__ void ldm_x4(uint32_t r[4], uint32_t addr) {
    asm volatile("ldmatrix.sync.aligned.m8n8.x4.shared.b16 {%0,%1,%2,%3}, [%4];"
                 : "=r"(r[0]), "=r"(r[1]), "=r"(r[2]), "=r"(r[3]) : "r"(addr));
}

__device__ __forceinline__ void cpasync16(uint32_t dst, const void* src) {
    asm volatile("cp.async.cg.shared.global [%0], [%1], 16;" :: "r"(dst), "l"(src)
                 : "memory");
}

__device__ __forceinline__ void red2(float* p, float a, float b) {
    asm volatile("red.global.add.v2.f32 [%0], {%1, %2};" :: "l"(p), "f"(a), "f"(b) : "memory");
}

__device__ __forceinline__ long long load_idx(const void* p, long long i, int is64) {
    if (is64) return ((const long long*)p)[i];
    return (long long)((const int*)p)[i];
}

// chunk index -> weight matrix / k-offset / K stride
__device__ __forceinline__ void chunk_src(int gc, const __nv_bfloat16*& w, int& c0, int& Kl) {
    if (gc < 5)      { w = g_W1T;  c0 = gc * 64;       Kl = K1; }
    else if (gc < 9) { w = g_W2T;  c0 = (gc - 5) * 64; Kl = K23; }
    else             { w = g_WsvT; c0 = (gc - 9) * 64; Kl = K23; }
}

// ---------------- small helper kernels ----------------
__global__ void detect_idx_kernel(const int* __restrict__ idx32) {
    __shared__ int nz;
    if (threadIdx.x == 0) nz = 0;
    __syncthreads();
    int v = idx32[2 * threadIdx.x + 1];
    if (v != 0) atomicOr(&nz, 1);
    __syncthreads();
    if (threadIdx.x == 0) g_idx64 = (nz == 0) ? 1 : 0;
}

__global__ void init_out_kernel(const float4* __restrict__ s, const float4* __restrict__ v,
                                float4* __restrict__ out, int ns4, int nv4) {
    int stride = gridDim.x * blockDim.x;
    for (int i = blockIdx.x * blockDim.x + threadIdx.x; i < ns4; i += stride) out[i] = s[i];
    for (int i = blockIdx.x * blockDim.x + threadIdx.x; i < nv4; i += stride)
        out[ns4 + i] = v[i];
}

__global__ void prep_weights(const float* __restrict__ W1, const float* __restrict__ W2,
                             const float* __restrict__ Ws, const float* __restrict__ Wv) {
    const int t1 = 256 * K1;
    const int t2 = t1 + 256 * K23;
    const int t3 = t2 + 256 * K23;
    int stride = gridDim.x * blockDim.x;
    for (int idx = blockIdx.x * blockDim.x + threadIdx.x; idx < t3; idx += stride) {
        if (idx < t1) {
            int n = idx / K1, k = idx % K1;
            g_W1T[idx] = __float2bfloat16((k < IN_DIM) ? W1[k * 256 + n] : 0.0f);
        } else if (idx < t2) {
            int r = idx - t1;
            int n = r / K23, k = r % K23;
            g_W2T[r] = __float2bfloat16(W2[k * 256 + n]);
        } else {
            int r = idx - t2;
            int n = r / K23, k = r % K23;
            float val = (n < FDIM) ? Ws[k * FDIM + n] : Wv[k * FDIM + (n - FDIM)];
            g_WsvT[r] = __float2bfloat16(val);
        }
    }
}

// ---------------- main fused kernel ----------------
__global__ __launch_bounds__(NTHREADS, 1)
void painn_mma_kernel(const float* __restrict__ s, const float* __restrict__ pos,
                      const void* __restrict__ eidx,
                      const float* __restrict__ b1, const float* __restrict__ b2,
                      const float* __restrict__ bs, const float* __restrict__ bv,
                      const float* __restrict__ centers, const float* __restrict__ widths,
                      float* __restrict__ out_s, float* __restrict__ out_v, int E) {
    extern __shared__ char smem[];
    uint32_t* A32 = (uint32_t*)smem;                    // [128][164] bf16 pairs
    int* dstS = (int*)(smem + DST_OFF);
    float* dirS = (float*)(smem + DIR_OFF);
    const uint32_t Abase = smem_u32(smem);
    const uint32_t Bb[2] = {Abase + B0_OFF, Abase + B1_OFF};

    const int tid = threadIdx.x;
    const int wid = tid >> 5;
    const int lane = tid & 31;
    const int g = lane >> 2;
    const int tig = lane & 3;
    const int quad = lane >> 3;
    const int rowin = lane & 7;
    const int warp_m = wid & 3;     // 4 M-warps x 32 rows
    const int warp_n = wid >> 2;    // 4 N-warps x 64 cols
    const int m0 = warp_m * 32;
    const int n0 = warp_n * 64;

    const int is64 = g_idx64;
    const long long e0 = (long long)blockIdx.x * TILE_E;

    // staging geometry: thread covers half a B row (64B), 4x cp.async 16B
    const int srow = tid >> 1;
    const int ssub = (tid & 1) * 4;   // 16B-unit within row

    // ---- prologue: issue stage of chunk 0 ----
    {
        const __nv_bfloat16* w; int c0, Kl;
        chunk_src(0, w, c0, Kl);
        const char* src = (const char*)(w + (size_t)srow * Kl + c0) + ssub * 16;
        uint32_t dst = Bb[0] + srow * BROW_BYTES + ssub * 16;
#pragma unroll
        for (int i = 0; i < 4; ++i) cpasync16(dst + i * 16, src + i * 16);
        asm volatile("cp.async.commit_group;" ::: "memory");
    }

    // ---- build A + meta: 4 threads per edge (512 threads -> 128 edges) ----
    {
        const int m = tid >> 2;
        const int c = tid & 3;
        const bool valid = (e0 + m) < (long long)E;
        if (valid) {
            long long srcI = load_idx(eidx, e0 + m, is64);
            long long dstI = load_idx(eidx, (long long)E + e0 + m, is64);
            long long node = (c < 2) ? srcI : dstI;
            const float4* rp = (const float4*)(s + node * FDIM + (c & 1) * 64);
            uint32_t* Arow = A32 + m * APAIRS + c * 32;
#pragma unroll
            for (int q = 0; q < 16; ++q) {
                float4 t = __ldg(rp + q);
                Arow[2 * q]     = packbf(t.x, t.y);
                Arow[2 * q + 1] = packbf(t.z, t.w);
            }
            if (c == 0) {
                float rx = pos[dstI * 3 + 0] - pos[srcI * 3 + 0];
                float ry = pos[dstI * 3 + 1] - pos[srcI * 3 + 1];
                float rz = pos[dstI * 3 + 2] - pos[srcI * 3 + 2];
                float d2 = rx * rx + ry * ry + rz * rz;
                float dist = sqrtf(d2);
                float inv = (d2 > 0.f) ? (1.0f / dist) : 0.0f;
                dstS[m] = (int)dstI;
                dirS[m * 3 + 0] = rx * inv;
                dirS[m * 3 + 1] = ry * inv;
                dirS[m * 3 + 2] = rz * inv;
            } else if (c == 3) {
                float rx = pos[dstI * 3 + 0] - pos[srcI * 3 + 0];
                float ry = pos[dstI * 3 + 1] - pos[srcI * 3 + 1];
                float rz = pos[dstI * 3 + 2] - pos[srcI * 3 + 2];
                float dist = sqrtf(rx * rx + ry * ry + rz * rz);
                uint32_t* Ar = A32 + m * APAIRS + 128;
#pragma unroll
                for (int j = 0; j < 32; ++j) {
                    float f0 = 0.f, f1 = 0.f;
                    int j0 = 2 * j, j1 = 2 * j + 1;
                    if (j0 < NRBF) {
                        float t = (dist - __ldg(centers + j0)) / (__ldg(widths + j0) + 1e-8f);
                        f0 = __expf(-t * t);
                    }
                    if (j1 < NRBF) {
                        float t = (dist - __ldg(centers + j1)) / (__ldg(widths + j1) + 1e-8f);
                        f1 = __expf(-t * t);
                    }
                    Ar[j] = packbf(f0, f1);
                }
                A32[m * APAIRS + 160] = 0; A32[m * APAIRS + 161] = 0;
                A32[m * APAIRS + 162] = 0; A32[m * APAIRS + 163] = 0;
            }
        } else {
            uint32_t* Arow = A32 + m * APAIRS + c * 32;
#pragma unroll
            for (int q = 0; q < 32; ++q) Arow[q] = 0;
            if (c == 0) dstS[m] = -1;
            if (c == 3) {
                uint32_t* Ar = A32 + m * APAIRS + 128;
#pragma unroll
                for (int j = 0; j < 36; ++j) Ar[j] = 0;
            }
        }
    }

    float acc[2][8][4];
    int gc = 0;

#pragma unroll 1
    for (int L = 0; L < 3; ++L) {
        const int nch = (L == 0) ? 5 : 4;

#pragma unroll
        for (int mb = 0; mb < 2; ++mb)
#pragma unroll
            for (int t = 0; t < 8; ++t)
#pragma unroll
                for (int i = 0; i < 4; ++i) acc[mb][t][i] = 0.f;

#pragma unroll 1
        for (int c = 0; c < nch; ++c) {
            const int gcl = gc;                     // this chunk
            const int c0 = (L == 0) ? c * 64 : c * 64;
            __syncthreads();   // all consumers of buf[(gcl+1)&1] are done
            if (gcl + 1 < NCHUNK_TOT) {             // issue stage of next chunk
                const __nv_bfloat16* w; int nc0, nKl;
                chunk_src(gcl + 1, w, nc0, nKl);
                const char* src = (const char*)(w + (size_t)srow * nKl + nc0) + ssub * 16;
                uint32_t dst = Bb[(gcl + 1) & 1] + srow * BROW_BYTES + ssub * 16;
#pragma unroll
                for (int i = 0; i < 4; ++i) cpasync16(dst + i * 16, src + i * 16);
                asm volatile("cp.async.commit_group;" ::: "memory");
                asm volatile("cp.async.wait_group 1;" ::: "memory");
            } else {
                asm volatile("cp.async.wait_group 0;" ::: "memory");
            }
            __syncthreads();   // buf[gcl&1] visible to everyone

            const uint32_t Bc = Bb[gcl & 1];
#pragma unroll
            for (int ks = 0; ks < 4; ++ks) {
                const int KPa = (c0 >> 1) + ks * 8;
                const int KB = ks * 8;
                uint32_t afr[2][4];
#pragma unroll
                for (int mb = 0; mb < 2; ++mb) {
                    int row = m0 + mb * 16 + (quad & 1) * 8 + rowin;
                    int kp = KPa + (quad >> 1) * 4;
                    ldm_x4(afr[mb], Abase + (uint32_t)(row * APAIRS + kp) * 4u);
                }
#pragma unroll
                for (int tp = 0; tp < 4; ++tp) {
                    uint32_t bfr[4];
                    int n = n0 + tp * 16 + (quad >> 1) * 8 + rowin;
                    int kp = KB + (quad & 1) * 4;
                    ldm_x4(bfr, Bc + (uint32_t)(n * 36 + kp) * 4u);
#pragma unroll
                    for (int mb = 0; mb < 2; ++mb) {
                        mma16816(acc[mb][2 * tp], afr[mb][0], afr[mb][1], afr[mb][2],
                                 afr[mb][3], bfr[0], bfr[1]);
                        mma16816(acc[mb][2 * tp + 1], afr[mb][0], afr[mb][1], afr[mb][2],
                                 afr[mb][3], bfr[2], bfr[3]);
                    }
                }
            }
            gc++;
        }
        __syncthreads();   // layer compute done everywhere before A overwrite / scatter

        if (L < 2) {
            const float* bias = (L == 0) ? b1 : b2;
#pragma unroll
            for (int mb = 0; mb < 2; ++mb) {
                const int r0 = m0 + mb * 16 + g;
#pragma unroll
                for (int t = 0; t < 8; ++t) {
                    const int col = n0 + t * 8 + tig * 2;
                    float bb0 = __ldg(bias + col);
                    float bb1 = __ldg(bias + col + 1);
                    const int pr = col >> 1;
                    A32[r0 * APAIRS + pr] =
                        packbf(silu(acc[mb][t][0] + bb0), silu(acc[mb][t][1] + bb1));
                    A32[(r0 + 8) * APAIRS + pr] =
                        packbf(silu(acc[mb][t][2] + bb0), silu(acc[mb][t][3] + bb1));
                }
            }
        } else {
            // scatter: warp_n 0,1 -> ds; warp_n 2,3 -> dv
#pragma unroll
            for (int mb = 0; mb < 2; ++mb) {
                const int r0 = m0 + mb * 16 + g, r1 = r0 + 8;
                const int d0 = dstS[r0], d1 = dstS[r1];
                if (n0 < 128) {
#pragma unroll
                    for (int t = 0; t < 8; ++t) {
                        const int col = n0 + t * 8 + tig * 2;
                        float bb0 = __ldg(bs + col), bb1 = __ldg(bs + col + 1);
                        if (d0 >= 0)
                            red2(out_s + (long long)d0 * FDIM + col, acc[mb][t][0] + bb0,
                                 acc[mb][t][1] + bb1);
                        if (d1 >= 0)
                            red2(out_s + (long long)d1 * FDIM + col, acc[mb][t][2] + bb0,
                                 acc[mb][t][3] + bb1);
                    }
                } else {
                    float dx0 = dirS[r0 * 3], dy0 = dirS[r0 * 3 + 1], dz0 = dirS[r0 * 3 + 2];
                    float dx1 = dirS[r1 * 3], dy1 = dirS[r1 * 3 + 1], dz1 = dirS[r1 * 3 + 2];
#pragma unroll
                    for (int t = 0; t < 8; ++t) {
                        const int col = n0 - 128 + t * 8 + tig * 2;
                        float bb0 = __ldg(bv + col), bb1 = __ldg(bv + col + 1);
                        if (d0 >= 0) {
                            float v0 = acc[mb][t][0] + bb0, v1 = acc[mb][t][1] + bb1;
                            float* vb = out_v + (long long)d0 * 3 * FDIM + col;
                            red2(vb, dx0 * v0, dx0 * v1);
                            red2(vb + FDIM, dy0 * v0, dy0 * v1);
                            red2(vb + 2 * FDIM, dz0 * v0, dz0 * v1);
                        }
                        if (d1 >= 0) {
                            float v0 = acc[mb][t][2] + bb0, v1 = acc[mb][t][3] + bb1;
                            float* vb = out_v + (long long)d1 * 3 * FDIM + col;
                            red2(vb, dx1 * v0, dx1 * v1);
                            red2(vb + FDIM, dy1 * v0, dy1 * v1);
                            red2(vb + 2 * FDIM, dz1 * v0, dz1 * v1);
                        }
                    }
                }
            }
        }
    }
}

// ---------------- launcher ----------------
extern "C" void kernel_launch(void* const* d_in, const int* in_sizes, int n_in,
                              void* d_out, int out_size) {
    const float* s       = (const float*)d_in[0];
    const float* v       = (const float*)d_in[1];
    const float* pos     = (const float*)d_in[2];
    const void*  eidx    = d_in[3];
    const float* W1      = (const float*)d_in[4];
    const float* b1      = (const float*)d_in[5];
    const float* W2      = (const float*)d_in[6];
    const float* b2      = (const float*)d_in[7];
    const float* Ws      = (const float*)d_in[8];
    const float* bs      = (const float*)d_in[9];
    const float* Wv      = (const float*)d_in[10];
    const float* bv      = (const float*)d_in[11];
    const float* centers = (const float*)d_in[12];
    const float* widths  = (const float*)d_in[13];

    int N = in_sizes[0] / FDIM;
    int E = in_sizes[3] / 2;

    float* out_s = (float*)d_out;
    float* out_v = out_s + (long long)N * FDIM;

    detect_idx_kernel<<<1, 256>>>((const int*)eidx);

    int ns4 = N * FDIM / 4;
    int nv4 = N * 3 * FDIM / 4;
    init_out_kernel<<<1024, 256>>>((const float4*)s, (const float4*)v, (float4*)d_out, ns4, nv4);

    prep_weights<<<256, 256>>>(W1, W2, Ws, Wv);

    cudaFuncSetAttribute(painn_mma_kernel, cudaFuncAttributeMaxDynamicSharedMemorySize,
                         SMEM_TOTAL);

    int grid = (E + TILE_E - 1) / TILE_E;
    painn_mma_kernel<<<grid, NTHREADS, SMEM_TOTAL>>>(s, pos, eidx, b1, b2, bs, bv, centers,
                                                     widths, out_s, out_v, E);
}

// round 10
// speedup vs baseline: 5.0562x; 1.0824x over previous
#include <cuda_runtime.h>
#include <cuda_bf16.h>
#include <cstdint>
#include <math.h>

// PaiNN interaction — fused HMMA bf16 kernel, round 10.
// R9 profile: issue 19.8%, tensor 23.3%, L1 39%, L2 28% -> serialization-bound
// (2 barriers x 13 chunks + bursty ldmatrix after each). This round: 3-stage
// cp.async ring with ONE barrier per chunk; barriers land between compute runs.
//
// Inputs: 0 s [N,128] f32, 1 v [N,3,128] f32, 2 pos [N,3] f32, 3 edge_index [2,E],
// 4 W1 [276,256], 5 b1, 6 W2, 7 b2, 8 Ws, 9 bs, 10 Wv, 11 bv, 12 centers, 13 widths
// Output: concat(s_out [N,128], v_out [N,3,128]) f32.

#define FDIM 128
#define NRBF 20
#define IN_DIM 276
#define K1 320
#define K23 256
#define TILE_E 128
#define NTHREADS 512
#define NCHUNK_TOT 13        // 5 + 4 + 4
#define NSTAGE 3

#define APAIRS 164           // u32 per A row (328 bf16); 164 % 32 == 4 (bank-perfect)
#define A_BYTES (TILE_E * APAIRS * 4)            // 83968
#define BROW_BYTES 144       // 72 bf16 per B row (36 u32); 36 % 32 == 4
#define B_BYTES (256 * BROW_BYTES)               // 36864
#define DST_OFF (A_BYTES + NSTAGE * B_BYTES)
#define DIR_OFF (DST_OFF + 512)
#define SMEM_TOTAL (DIR_OFF + 1536)              // ~196KB -> 1 CTA/SM

// ---------------- device globals ----------------
__device__ __align__(16) __nv_bfloat16 g_W1T[256 * K1];    // [n][k], k>=276 zero
__device__ __align__(16) __nv_bfloat16 g_W2T[256 * K23];
__device__ __align__(16) __nv_bfloat16 g_WsvT[256 * K23];  // n<128 Ws, n>=128 Wv
__device__ int g_idx64;

// ---------------- helpers ----------------
__device__ __forceinline__ uint32_t smem_u32(const void* p) {
    uint32_t a;
    asm("{ .reg .u64 t; cvta.to.shared.u64 t, %1; cvt.u32.u64 %0, t; }" : "=r"(a) : "l"(p));
    return a;
}
__device__ __forceinline__ uint32_t packbf(float a, float b) {
    __nv_bfloat162 h = __floats2bfloat162_rn(a, b);
    return *reinterpret_cast<uint32_t*>(&h);
}
__device__ __forceinline__ float silu(float x) { return x / (1.0f + __expf(-x)); }

__device__ __forceinline__ void mma16816(float c[4], uint32_t a0, uint32_t a1, uint32_t a2,
                                         uint32_t a3, uint32_t b0, uint32_t b1) {
    asm volatile(
        "mma.sync.aligned.m16n8k16.row.col.f32.bf16.bf16.f32 "
        "{%0,%1,%2,%3}, {%4,%5,%6,%7}, {%8,%9}, {%0,%1,%2,%3};"
        : "+f"(c[0]), "+f"(c[1]), "+f"(c[2]), "+f"(c[3])
        : "r"(a0), "r"(a1), "r"(a2), "r"(a3), "r"(b0), "r"(b1));
}

__device__ __forceinline__ void ldm_x4(uint32_t r[4], uint32_t addr) {
    asm volatile("ldmatrix.sync.aligned.m8n8.x4.shared.b16 {%0,%1,%2,%3}, [%4];"
                 : "=r"(r[0]), "=r"(r[1]), "=r"(r[2]), "=r"(r[3]) : "r"(addr));
}

__device__ __forceinline__ void cpasync16(uint32_t dst, const void* src) {
    asm volatile("cp.async.cg.shared.global [%0], [%1], 16;" :: "r"(dst), "l"(src)
                 : "memory");
}

__device__ __forceinline__ void red2(float* p, float a, float b) {
    asm volatile("red.global.add.v2.f32 [%0], {%1, %2};" :: "l"(p), "f"(a), "f"(b) : "memory");
}

__device__ __forceinline__ long long load_idx(const void* p, long long i, int is64) {
    if (is64) return ((const long long*)p)[i];
    return (long long)((const int*)p)[i];
}

// chunk index -> weight matrix / k-offset / K stride
__device__ __forceinline__ void chunk_src(int gc, const __nv_bfloat16*& w, int& c0, int& Kl) {
    if (gc < 5)      { w = g_W1T;  c0 = gc * 64;       Kl = K1; }
    else if (gc < 9) { w = g_W2T;  c0 = (gc - 5) * 64; Kl = K23; }
    else             { w = g_WsvT; c0 = (gc - 9) * 64; Kl = K23; }
}

// ---------------- small helper kernels ----------------
__global__ void detect_idx_kernel(const int* __restrict__ idx32) {
    __shared__ int nz;
    if (threadIdx.x == 0) nz = 0;
    __syncthreads();
    int v = idx32[2 * threadIdx.x + 1];
    if (v != 0) atomicOr(&nz, 1);
    __syncthreads();
    if (threadIdx.x == 0) g_idx64 = (nz == 0) ? 1 : 0;
}

__global__ void init_out_kernel(const float4* __restrict__ s, const float4* __restrict__ v,
                                float4* __restrict__ out, int ns4, int nv4) {
    int stride = gridDim.x * blockDim.x;
    for (int i = blockIdx.x * blockDim.x + threadIdx.x; i < ns4; i += stride) out[i] = s[i];
    for (int i = blockIdx.x * blockDim.x + threadIdx.x; i < nv4; i += stride)
        out[ns4 + i] = v[i];
}

__global__ void prep_weights(const float* __restrict__ W1, const float* __restrict__ W2,
                             const float* __restrict__ Ws, const float* __restrict__ Wv) {
    const int t1 = 256 * K1;
    const int t2 = t1 + 256 * K23;
    const int t3 = t2 + 256 * K23;
    int stride = gridDim.x * blockDim.x;
    for (int idx = blockIdx.x * blockDim.x + threadIdx.x; idx < t3; idx += stride) {
        if (idx < t1) {
            int n = idx / K1, k = idx % K1;
            g_W1T[idx] = __float2bfloat16((k < IN_DIM) ? W1[k * 256 + n] : 0.0f);
        } else if (idx < t2) {
            int r = idx - t1;
            int n = r / K23, k = r % K23;
            g_W2T[r] = __float2bfloat16(W2[k * 256 + n]);
        } else {
            int r = idx - t2;
            int n = r / K23, k = r % K23;
            float val = (n < FDIM) ? Ws[k * FDIM + n] : Wv[k * FDIM + (n - FDIM)];
            g_WsvT[r] = __float2bfloat16(val);
        }
    }
}

// ---------------- main fused kernel ----------------
__global__ __launch_bounds__(NTHREADS, 1)
void painn_mma_kernel(const float* __restrict__ s, const float* __restrict__ pos,
                      const void* __restrict__ eidx,
                      const float* __restrict__ b1, const float* __restrict__ b2,
                      const float* __restrict__ bs, const float* __restrict__ bv,
                      const float* __restrict__ centers, const float* __restrict__ widths,
                      float* __restrict__ out_s, float* __restrict__ out_v, int E) {
    extern __shared__ char smem[];
    uint32_t* A32 = (uint32_t*)smem;                    // [128][164] bf16 pairs
    int* dstS = (int*)(smem + DST_OFF);
    float* dirS = (float*)(smem + DIR_OFF);
    const uint32_t Abase = smem_u32(smem);

    const int tid = threadIdx.x;
    const int wid = tid >> 5;
    const int lane = tid & 31;
    const int g = lane >> 2;
    const int tig = lane & 3;
    const int quad = lane >> 3;
    const int rowin = lane & 7;
    const int warp_m = wid & 3;     // 4 M-warps x 32 rows
    const int warp_n = wid >> 2;    // 4 N-warps x 64 cols
    const int m0 = warp_m * 32;
    const int n0 = warp_n * 64;

    const int is64 = g_idx64;
    const long long e0 = (long long)blockIdx.x * TILE_E;

    // staging geometry: thread covers half a B row (64B), 4x cp.async 16B
    const int srow = tid >> 1;
    const int ssub = (tid & 1) * 4;

    // ---- prologue: issue stage of chunk 0 into ring slot 0 ----
    {
        const __nv_bfloat16* w; int c0, Kl;
        chunk_src(0, w, c0, Kl);
        const char* src = (const char*)(w + (size_t)srow * Kl + c0) + ssub * 16;
        uint32_t dst = Abase + A_BYTES + srow * BROW_BYTES + ssub * 16;
#pragma unroll
        for (int i = 0; i < 4; ++i) cpasync16(dst + i * 16, src + i * 16);
        asm volatile("cp.async.commit_group;" ::: "memory");
    }

    // ---- build A + meta: 4 threads per edge ----
    {
        const int m = tid >> 2;
        const int c = tid & 3;
        const bool valid = (e0 + m) < (long long)E;
        if (valid) {
            long long srcI = load_idx(eidx, e0 + m, is64);
            long long dstI = load_idx(eidx, (long long)E + e0 + m, is64);
            long long node = (c < 2) ? srcI : dstI;
            const float4* rp = (const float4*)(s + node * FDIM + (c & 1) * 64);
            uint32_t* Arow = A32 + m * APAIRS + c * 32;
#pragma unroll
            for (int q = 0; q < 16; ++q) {
                float4 t = __ldg(rp + q);
                Arow[2 * q]     = packbf(t.x, t.y);
                Arow[2 * q + 1] = packbf(t.z, t.w);
            }
            if (c == 0) {
                float rx = pos[dstI * 3 + 0] - pos[srcI * 3 + 0];
                float ry = pos[dstI * 3 + 1] - pos[srcI * 3 + 1];
                float rz = pos[dstI * 3 + 2] - pos[srcI * 3 + 2];
                float d2 = rx * rx + ry * ry + rz * rz;
                float dist = sqrtf(d2);
                float inv = (d2 > 0.f) ? (1.0f / dist) : 0.0f;
                dstS[m] = (int)dstI;
                dirS[m * 3 + 0] = rx * inv;
                dirS[m * 3 + 1] = ry * inv;
                dirS[m * 3 + 2] = rz * inv;
            } else if (c == 3) {
                float rx = pos[dstI * 3 + 0] - pos[srcI * 3 + 0];
                float ry = pos[dstI * 3 + 1] - pos[srcI * 3 + 1];
                float rz = pos[dstI * 3 + 2] - pos[srcI * 3 + 2];
                float dist = sqrtf(rx * rx + ry * ry + rz * rz);
                uint32_t* Ar = A32 + m * APAIRS + 128;
#pragma unroll
                for (int j = 0; j < 32; ++j) {
                    float f0 = 0.f, f1 = 0.f;
                    int j0 = 2 * j, j1 = 2 * j + 1;
                    if (j0 < NRBF) {
                        float t = (dist - __ldg(centers + j0)) / (__ldg(widths + j0) + 1e-8f);
                        f0 = __expf(-t * t);
                    }
                    if (j1 < NRBF) {
                        float t = (dist - __ldg(centers + j1)) / (__ldg(widths + j1) + 1e-8f);
                        f1 = __expf(-t * t);
                    }
                    Ar[j] = packbf(f0, f1);
                }
                A32[m * APAIRS + 160] = 0; A32[m * APAIRS + 161] = 0;
                A32[m * APAIRS + 162] = 0; A32[m * APAIRS + 163] = 0;
            }
        } else {
            uint32_t* Arow = A32 + m * APAIRS + c * 32;
#pragma unroll
            for (int q = 0; q < 32; ++q) Arow[q] = 0;
            if (c == 0) dstS[m] = -1;
            if (c == 3) {
                uint32_t* Ar = A32 + m * APAIRS + 128;
#pragma unroll
                for (int j = 0; j < 36; ++j) Ar[j] = 0;
            }
        }
    }

    float acc[2][8][4];
    int gc = 0;

#pragma unroll 1
    for (int L = 0; L < 3; ++L) {
        const int nch = (L == 0) ? 5 : 4;

#pragma unroll
        for (int mb = 0; mb < 2; ++mb)
#pragma unroll
            for (int t = 0; t < 8; ++t)
#pragma unroll
                for (int i = 0; i < 4; ++i) acc[mb][t][i] = 0.f;

#pragma unroll 1
        for (int c = 0; c < nch; ++c) {
            const int gcl = gc;
            const int c0 = c * 64;
            // stage NEXT chunk into ring slot (gcl+1)%3 (overwrites slot of gcl-2,
            // whose consumers all finished before the previous barrier)
            if (gcl + 1 < NCHUNK_TOT) {
                const __nv_bfloat16* w; int nc0, nKl;
                chunk_src(gcl + 1, w, nc0, nKl);
                const char* src = (const char*)(w + (size_t)srow * nKl + nc0) + ssub * 16;
                uint32_t dst = Abase + A_BYTES + ((gcl + 1) % NSTAGE) * B_BYTES +
                               srow * BROW_BYTES + ssub * 16;
#pragma unroll
                for (int i = 0; i < 4; ++i) cpasync16(dst + i * 16, src + i * 16);
                asm volatile("cp.async.commit_group;" ::: "memory");
                asm volatile("cp.async.wait_group 1;" ::: "memory");
            } else {
                asm volatile("cp.async.wait_group 0;" ::: "memory");
            }
            __syncthreads();   // publish chunk gcl (and A after layer epilogues)

            const uint32_t Bc = Abase + A_BYTES + (gcl % NSTAGE) * B_BYTES;
#pragma unroll
            for (int ks = 0; ks < 4; ++ks) {
                const int KPa = (c0 >> 1) + ks * 8;
                const int KB = ks * 8;
                uint32_t afr[2][4];
#pragma unroll
                for (int mb = 0; mb < 2; ++mb) {
                    int row = m0 + mb * 16 + (quad & 1) * 8 + rowin;
                    int kp = KPa + (quad >> 1) * 4;
                    ldm_x4(afr[mb], Abase + (uint32_t)(row * APAIRS + kp) * 4u);
                }
#pragma unroll
                for (int tp = 0; tp < 4; ++tp) {
                    uint32_t bfr[4];
                    int n = n0 + tp * 16 + (quad >> 1) * 8 + rowin;
                    int kp = KB + (quad & 1) * 4;
                    ldm_x4(bfr, Bc + (uint32_t)(n * 36 + kp) * 4u);
#pragma unroll
                    for (int mb = 0; mb < 2; ++mb) {
                        mma16816(acc[mb][2 * tp], afr[mb][0], afr[mb][1], afr[mb][2],
                                 afr[mb][3], bfr[0], bfr[1]);
                        mma16816(acc[mb][2 * tp + 1], afr[mb][0], afr[mb][1], afr[mb][2],
                                 afr[mb][3], bfr[2], bfr[3]);
                    }
                }
            }
            gc++;
        }
        __syncthreads();   // layer compute done before A overwrite / scatter

        if (L < 2) {
            const float* bias = (L == 0) ? b1 : b2;
#pragma unroll
            for (int mb = 0; mb < 2; ++mb) {
                const int r0 = m0 + mb * 16 + g;
#pragma unroll
                for (int t = 0; t < 8; ++t) {
                    const int col = n0 + t * 8 + tig * 2;
                    float bb0 = __ldg(bias + col);
                    float bb1 = __ldg(bias + col + 1);
                    const int pr = col >> 1;
                    A32[r0 * APAIRS + pr] =
                        packbf(silu(acc[mb][t][0] + bb0), silu(acc[mb][t][1] + bb1));
                    A32[(r0 + 8) * APAIRS + pr] =
                        packbf(silu(acc[mb][t][2] + bb0), silu(acc[mb][t][3] + bb1));
                }
            }
            // next chunk iteration's __syncthreads publishes these A writes
        } else {
            // scatter: warp_n 0,1 -> ds; warp_n 2,3 -> dv
#pragma unroll
            for (int mb = 0; mb < 2; ++mb) {
                const int r0 = m0 + mb * 16 + g, r1 = r0 + 8;
                const int d0 = dstS[r0], d1 = dstS[r1];
                if (n0 < 128) {
#pragma unroll
                    for (int t = 0; t < 8; ++t) {
                        const int col = n0 + t * 8 + tig * 2;
                        float bb0 = __ldg(bs + col), bb1 = __ldg(bs + col + 1);
                        if (d0 >= 0)
                            red2(out_s + (long long)d0 * FDIM + col, acc[mb][t][0] + bb0,
                                 acc[mb][t][1] + bb1);
                        if (d1 >= 0)
                            red2(out_s + (long long)d1 * FDIM + col, acc[mb][t][2] + bb0,
                                 acc[mb][t][3] + bb1);
                    }
                } else {
                    float dx0 = dirS[r0 * 3], dy0 = dirS[r0 * 3 + 1], dz0 = dirS[r0 * 3 + 2];
                    float dx1 = dirS[r1 * 3], dy1 = dirS[r1 * 3 + 1], dz1 = dirS[r1 * 3 + 2];
#pragma unroll
                    for (int t = 0; t < 8; ++t) {
                        const int col = n0 - 128 + t * 8 + tig * 2;
                        float bb0 = __ldg(bv + col), bb1 = __ldg(bv + col + 1);
                        if (d0 >= 0) {
                            float v0 = acc[mb][t][0] + bb0, v1 = acc[mb][t][1] + bb1;
                            float* vb = out_v + (long long)d0 * 3 * FDIM + col;
                            red2(vb, dx0 * v0, dx0 * v1);
                            red2(vb + FDIM, dy0 * v0, dy0 * v1);
                            red2(vb + 2 * FDIM, dz0 * v0, dz0 * v1);
                        }
                        if (d1 >= 0) {
                            float v0 = acc[mb][t][2] + bb0, v1 = acc[mb][t][3] + bb1;
                            float* vb = out_v + (long long)d1 * 3 * FDIM + col;
                            red2(vb, dx1 * v0, dx1 * v1);
                            red2(vb + FDIM, dy1 * v0, dy1 * v1);
                            red2(vb + 2 * FDIM, dz1 * v0, dz1 * v1);
                        }
                    }
                }
            }
        }
    }
}

// ---------------- launcher ----------------
extern "C" void kernel_launch(void* const* d_in, const int* in_sizes, int n_in,
                              void* d_out, int out_size) {
    const float* s       = (const float*)d_in[0];
    const float* v       = (const float*)d_in[1];
    const float* pos     = (const float*)d_in[2];
    const void*  eidx    = d_in[3];
    const float* W1      = (const float*)d_in[4];
    const float* b1      = (const float*)d_in[5];
    const float* W2      = (const float*)d_in[6];
    const float* b2      = (const float*)d_in[7];
    const float* Ws      = (const float*)d_in[8];
    const float* bs      = (const float*)d_in[9];
    const float* Wv      = (const float*)d_in[10];
    const float* bv      = (const float*)d_in[11];
    const float* centers = (const float*)d_in[12];
    const float* widths  = (const float*)d_in[13];

    int N = in_sizes[0] / FDIM;
    int E = in_sizes[3] / 2;

    float* out_s = (float*)d_out;
    float* out_v = out_s + (long long)N * FDIM;

    detect_idx_kernel<<<1, 256>>>((const int*)eidx);

    int ns4 = N * FDIM / 4;
    int nv4 = N * 3 * FDIM / 4;
    init_out_kernel<<<1024, 256>>>((const float4*)s, (const float4*)v, (float4*)d_out, ns4, nv4);

    prep_weights<<<256, 256>>>(W1, W2, Ws, Wv);

    cudaFuncSetAttribute(painn_mma_kernel, cudaFuncAttributeMaxDynamicSharedMemorySize,
                         SMEM_TOTAL);

    int grid = (E + TILE_E - 1) / TILE_E;
    painn_mma_kernel<<<grid, NTHREADS, SMEM_TOTAL>>>(s, pos, eidx, b1, b2, bs, bv, centers,
                                                     widths, out_s, out_v, E);
}

// round 11
// speedup vs baseline: 5.7607x; 1.1393x over previous
#include <cuda_runtime.h>
#include <cuda_bf16.h>
#include <cstdint>
#include <math.h>

// PaiNN interaction — fused HMMA bf16 kernel, round 11.
// R10: tensor 25.3%, issue 21.5%, occ 23.8% (16-warp cap) -> latency-bound.
// This round: 1024-thread CTA (32 warps, 50% occ), warp tile 32x32 (acc 32/thr
// to fit forced 64-reg budget), same 3-stage cp.async ring, 1 barrier/chunk.
//
// Inputs: 0 s [N,128] f32, 1 v [N,3,128] f32, 2 pos [N,3] f32, 3 edge_index [2,E],
// 4 W1 [276,256], 5 b1, 6 W2, 7 b2, 8 Ws, 9 bs, 10 Wv, 11 bv, 12 centers, 13 widths
// Output: concat(s_out [N,128], v_out [N,3,128]) f32.

#define FDIM 128
#define NRBF 20
#define IN_DIM 276
#define K1 320
#define K23 256
#define TILE_E 128
#define NTHREADS 1024
#define NCHUNK_TOT 13        // 5 + 4 + 4
#define NSTAGE 3

#define APAIRS 164           // u32 per A row (328 bf16); 164 % 32 == 4 (bank-perfect)
#define A_BYTES (TILE_E * APAIRS * 4)            // 83968
#define BROW_BYTES 144       // row stride in smem (36 u32; 36 % 32 == 4); 128B real
#define B_BYTES (256 * BROW_BYTES)               // 36864
#define DST_OFF (A_BYTES + NSTAGE * B_BYTES)
#define DIR_OFF (DST_OFF + 512)
#define SMEM_TOTAL (DIR_OFF + 1536)              // ~196KB -> 1 CTA/SM

// ---------------- device globals ----------------
__device__ __align__(16) __nv_bfloat16 g_W1T[256 * K1];    // [n][k], k>=276 zero
__device__ __align__(16) __nv_bfloat16 g_W2T[256 * K23];
__device__ __align__(16) __nv_bfloat16 g_WsvT[256 * K23];  // n<128 Ws, n>=128 Wv
__device__ int g_idx64;

// ---------------- helpers ----------------
__device__ __forceinline__ uint32_t smem_u32(const void* p) {
    uint32_t a;
    asm("{ .reg .u64 t; cvta.to.shared.u64 t, %1; cvt.u32.u64 %0, t; }" : "=r"(a) : "l"(p));
    return a;
}
__device__ __forceinline__ uint32_t packbf(float a, float b) {
    __nv_bfloat162 h = __floats2bfloat162_rn(a, b);
    return *reinterpret_cast<uint32_t*>(&h);
}
__device__ __forceinline__ float silu(float x) { return x / (1.0f + __expf(-x)); }

__device__ __forceinline__ void mma16816(float c[4], uint32_t a0, uint32_t a1, uint32_t a2,
                                         uint32_t a3, uint32_t b0, uint32_t b1) {
    asm volatile(
        "mma.sync.aligned.m16n8k16.row.col.f32.bf16.bf16.f32 "
        "{%0,%1,%2,%3}, {%4,%5,%6,%7}, {%8,%9}, {%0,%1,%2,%3};"
        : "+f"(c[0]), "+f"(c[1]), "+f"(c[2]), "+f"(c[3])
        : "r"(a0), "r"(a1), "r"(a2), "r"(a3), "r"(b0), "r"(b1));
}

__device__ __forceinline__ void ldm_x4(uint32_t r[4], uint32_t addr) {
    asm volatile("ldmatrix.sync.aligned.m8n8.x4.shared.b16 {%0,%1,%2,%3}, [%4];"
                 : "=r"(r[0]), "=r"(r[1]), "=r"(r[2]), "=r"(r[3]) : "r"(addr));
}

__device__ __forceinline__ void cpasync16(uint32_t dst, const void* src) {
    asm volatile("cp.async.cg.shared.global [%0], [%1], 16;" :: "r"(dst), "l"(src)
                 : "memory");
}

__device__ __forceinline__ void red2(float* p, float a, float b) {
    asm volatile("red.global.add.v2.f32 [%0], {%1, %2};" :: "l"(p), "f"(a), "f"(b) : "memory");
}

__device__ __forceinline__ long long load_idx(const void* p, long long i, int is64) {
    if (is64) return ((const long long*)p)[i];
    return (long long)((const int*)p)[i];
}

__device__ __forceinline__ void chunk_src(int gc, const __nv_bfloat16*& w, int& c0, int& Kl) {
    if (gc < 5)      { w = g_W1T;  c0 = gc * 64;       Kl = K1; }
    else if (gc < 9) { w = g_W2T;  c0 = (gc - 5) * 64; Kl = K23; }
    else             { w = g_WsvT; c0 = (gc - 9) * 64; Kl = K23; }
}

// ---------------- small helper kernels ----------------
__global__ void detect_idx_kernel(const int* __restrict__ idx32) {
    __shared__ int nz;
    if (threadIdx.x == 0) nz = 0;
    __syncthreads();
    int v = idx32[2 * threadIdx.x + 1];
    if (v != 0) atomicOr(&nz, 1);
    __syncthreads();
    if (threadIdx.x == 0) g_idx64 = (nz == 0) ? 1 : 0;
}

__global__ void init_out_kernel(const float4* __restrict__ s, const float4* __restrict__ v,
                                float4* __restrict__ out, int ns4, int nv4) {
    int stride = gridDim.x * blockDim.x;
    for (int i = blockIdx.x * blockDim.x + threadIdx.x; i < ns4; i += stride) out[i] = s[i];
    for (int i = blockIdx.x * blockDim.x + threadIdx.x; i < nv4; i += stride)
        out[ns4 + i] = v[i];
}

__global__ void prep_weights(const float* __restrict__ W1, const float* __restrict__ W2,
                             const float* __restrict__ Ws, const float* __restrict__ Wv) {
    const int t1 = 256 * K1;
    const int t2 = t1 + 256 * K23;
    const int t3 = t2 + 256 * K23;
    int stride = gridDim.x * blockDim.x;
    for (int idx = blockIdx.x * blockDim.x + threadIdx.x; idx < t3; idx += stride) {
        if (idx < t1) {
            int n = idx / K1, k = idx % K1;
            g_W1T[idx] = __float2bfloat16((k < IN_DIM) ? W1[k * 256 + n] : 0.0f);
        } else if (idx < t2) {
            int r = idx - t1;
            int n = r / K23, k = r % K23;
            g_W2T[r] = __float2bfloat16(W2[k * 256 + n]);
        } else {
            int r = idx - t2;
            int n = r / K23, k = r % K23;
            float val = (n < FDIM) ? Ws[k * FDIM + n] : Wv[k * FDIM + (n - FDIM)];
            g_WsvT[r] = __float2bfloat16(val);
        }
    }
}

// ---------------- main fused kernel ----------------
__global__ __launch_bounds__(NTHREADS, 1)
void painn_mma_kernel(const float* __restrict__ s, const float* __restrict__ pos,
                      const void* __restrict__ eidx,
                      const float* __restrict__ b1, const float* __restrict__ b2,
                      const float* __restrict__ bs, const float* __restrict__ bv,
                      const float* __restrict__ centers, const float* __restrict__ widths,
                      float* __restrict__ out_s, float* __restrict__ out_v, int E) {
    extern __shared__ char smem[];
    uint32_t* A32 = (uint32_t*)smem;                    // [128][164] bf16 pairs
    int* dstS = (int*)(smem + DST_OFF);
    float* dirS = (float*)(smem + DIR_OFF);
    const uint32_t Abase = smem_u32(smem);

    const int tid = threadIdx.x;
    const int wid = tid >> 5;
    const int lane = tid & 31;
    const int g = lane >> 2;
    const int tig = lane & 3;
    const int quad = lane >> 3;
    const int rowin = lane & 7;
    const int warp_m = wid & 3;     // 4 M-warps x 32 rows
    const int warp_n = wid >> 2;    // 8 N-warps x 32 cols
    const int m0 = warp_m * 32;
    const int n0 = warp_n * 32;

    const int is64 = g_idx64;
    const long long e0 = (long long)blockIdx.x * TILE_E;

    // B staging: 2048 16B-units (256 rows x 8); thread does units tid, tid+1024
    // ---- prologue: stage chunk 0 into ring slot 0 ----
    {
        const __nv_bfloat16* w; int c0, Kl;
        chunk_src(0, w, c0, Kl);
#pragma unroll
        for (int u = 0; u < 2; ++u) {
            int unit = tid + u * 1024;
            int row = unit >> 3, sub = unit & 7;
            cpasync16(Abase + A_BYTES + row * BROW_BYTES + sub * 16,
                      (const char*)(w + (size_t)row * Kl + c0) + sub * 16);
        }
        asm volatile("cp.async.commit_group;" ::: "memory");
    }

    // ---- build A + meta: 8 threads per edge (1024 threads -> 128 edges) ----
    {
        const int m = tid >> 3;
        const int c = tid & 7;
        const bool valid = (e0 + m) < (long long)E;
        if (valid) {
            long long srcI = load_idx(eidx, e0 + m, is64);
            long long dstI = load_idx(eidx, (long long)E + e0 + m, is64);
            long long node = (c < 4) ? srcI : dstI;
            const int qq = c & 3;   // quarter within node row
            const float4* rp = (const float4*)(s + node * FDIM) + qq * 8;
            uint32_t* Arow = A32 + m * APAIRS + c * 16;
#pragma unroll
            for (int q = 0; q < 8; ++q) {
                float4 t = __ldg(rp + q);
                Arow[2 * q]     = packbf(t.x, t.y);
                Arow[2 * q + 1] = packbf(t.z, t.w);
            }
            if (c == 0) {
                float rx = pos[dstI * 3 + 0] - pos[srcI * 3 + 0];
                float ry = pos[dstI * 3 + 1] - pos[srcI * 3 + 1];
                float rz = pos[dstI * 3 + 2] - pos[srcI * 3 + 2];
                float d2 = rx * rx + ry * ry + rz * rz;
                float dist = sqrtf(d2);
                float inv = (d2 > 0.f) ? (1.0f / dist) : 0.0f;
                dstS[m] = (int)dstI;
                dirS[m * 3 + 0] = rx * inv;
                dirS[m * 3 + 1] = ry * inv;
                dirS[m * 3 + 2] = rz * inv;
            } else if (c == 7) {
                float rx = pos[dstI * 3 + 0] - pos[srcI * 3 + 0];
                float ry = pos[dstI * 3 + 1] - pos[srcI * 3 + 1];
                float rz = pos[dstI * 3 + 2] - pos[srcI * 3 + 2];
                float dist = sqrtf(rx * rx + ry * ry + rz * rz);
                uint32_t* Ar = A32 + m * APAIRS + 128;
#pragma unroll
                for (int j = 0; j < 32; ++j) {
                    float f0 = 0.f, f1 = 0.f;
                    int j0 = 2 * j, j1 = 2 * j + 1;
                    if (j0 < NRBF) {
                        float t = (dist - __ldg(centers + j0)) / (__ldg(widths + j0) + 1e-8f);
                        f0 = __expf(-t * t);
                    }
                    if (j1 < NRBF) {
                        float t = (dist - __ldg(centers + j1)) / (__ldg(widths + j1) + 1e-8f);
                        f1 = __expf(-t * t);
                    }
                    Ar[j] = packbf(f0, f1);
                }
                A32[m * APAIRS + 160] = 0; A32[m * APAIRS + 161] = 0;
                A32[m * APAIRS + 162] = 0; A32[m * APAIRS + 163] = 0;
            }
        } else {
            uint32_t* Arow = A32 + m * APAIRS + c * 16;
#pragma unroll
            for (int q = 0; q < 16; ++q) Arow[q] = 0;
            if (c == 0) dstS[m] = -1;
            if (c == 7) {
                uint32_t* Ar = A32 + m * APAIRS + 128;
#pragma unroll
                for (int j = 0; j < 36; ++j) Ar[j] = 0;
            }
        }
    }

    float acc[2][4][4];   // [mb][2*tp+half][4]
    int gc = 0;

#pragma unroll 1
    for (int L = 0; L < 3; ++L) {
        const int nch = (L == 0) ? 5 : 4;

#pragma unroll
        for (int mb = 0; mb < 2; ++mb)
#pragma unroll
            for (int t = 0; t < 4; ++t)
#pragma unroll
                for (int i = 0; i < 4; ++i) acc[mb][t][i] = 0.f;

#pragma unroll 1
        for (int c = 0; c < nch; ++c) {
            const int gcl = gc;
            const int c0 = c * 64;
            if (gcl + 1 < NCHUNK_TOT) {
                const __nv_bfloat16* w; int nc0, nKl;
                chunk_src(gcl + 1, w, nc0, nKl);
                uint32_t slot = Abase + A_BYTES + ((gcl + 1) % NSTAGE) * B_BYTES;
#pragma unroll
                for (int u = 0; u < 2; ++u) {
                    int unit = tid + u * 1024;
                    int row = unit >> 3, sub = unit & 7;
                    cpasync16(slot + row * BROW_BYTES + sub * 16,
                              (const char*)(w + (size_t)row * nKl + nc0) + sub * 16);
                }
                asm volatile("cp.async.commit_group;" ::: "memory");
                asm volatile("cp.async.wait_group 1;" ::: "memory");
            } else {
                asm volatile("cp.async.wait_group 0;" ::: "memory");
            }
            __syncthreads();   // publish chunk gcl (and A after layer epilogues)

            const uint32_t Bc = Abase + A_BYTES + (gcl % NSTAGE) * B_BYTES;
#pragma unroll
            for (int ks = 0; ks < 4; ++ks) {
                const int KPa = (c0 >> 1) + ks * 8;
                const int KB = ks * 8;
                uint32_t afr[2][4];
#pragma unroll
                for (int mb = 0; mb < 2; ++mb) {
                    int row = m0 + mb * 16 + (quad & 1) * 8 + rowin;
                    int kp = KPa + (quad >> 1) * 4;
                    ldm_x4(afr[mb], Abase + (uint32_t)(row * APAIRS + kp) * 4u);
                }
#pragma unroll
                for (int tp = 0; tp < 2; ++tp) {
                    uint32_t bfr[4];
                    int n = n0 + tp * 16 + (quad >> 1) * 8 + rowin;
                    int kp = KB + (quad & 1) * 4;
                    ldm_x4(bfr, Bc + (uint32_t)(n * 36 + kp) * 4u);
#pragma unroll
                    for (int mb = 0; mb < 2; ++mb) {
                        mma16816(acc[mb][2 * tp], afr[mb][0], afr[mb][1], afr[mb][2],
                                 afr[mb][3], bfr[0], bfr[1]);
                        mma16816(acc[mb][2 * tp + 1], afr[mb][0], afr[mb][1], afr[mb][2],
                                 afr[mb][3], bfr[2], bfr[3]);
                    }
                }
            }
            gc++;
        }
        __syncthreads();   // layer compute done before A overwrite / scatter

        if (L < 2) {
            const float* bias = (L == 0) ? b1 : b2;
#pragma unroll
            for (int mb = 0; mb < 2; ++mb) {
                const int r0 = m0 + mb * 16 + g;
#pragma unroll
                for (int t = 0; t < 4; ++t) {
                    const int col = n0 + t * 8 + tig * 2;
                    float bb0 = __ldg(bias + col);
                    float bb1 = __ldg(bias + col + 1);
                    const int pr = col >> 1;
                    A32[r0 * APAIRS + pr] =
                        packbf(silu(acc[mb][t][0] + bb0), silu(acc[mb][t][1] + bb1));
                    A32[(r0 + 8) * APAIRS + pr] =
                        packbf(silu(acc[mb][t][2] + bb0), silu(acc[mb][t][3] + bb1));
                }
            }
            // next chunk iteration's __syncthreads publishes these A writes
        } else {
            // scatter: warp_n 0-3 -> ds (cols 0..127); warp_n 4-7 -> dv
#pragma unroll
            for (int mb = 0; mb < 2; ++mb) {
                const int r0 = m0 + mb * 16 + g, r1 = r0 + 8;
                const int d0 = dstS[r0], d1 = dstS[r1];
                if (n0 < 128) {
#pragma unroll
                    for (int t = 0; t < 4; ++t) {
                        const int col = n0 + t * 8 + tig * 2;
                        float bb0 = __ldg(bs + col), bb1 = __ldg(bs + col + 1);
                        if (d0 >= 0)
                            red2(out_s + (long long)d0 * FDIM + col, acc[mb][t][0] + bb0,
                                 acc[mb][t][1] + bb1);
                        if (d1 >= 0)
                            red2(out_s + (long long)d1 * FDIM + col, acc[mb][t][2] + bb0,
                                 acc[mb][t][3] + bb1);
                    }
                } else {
                    float dx0 = dirS[r0 * 3], dy0 = dirS[r0 * 3 + 1], dz0 = dirS[r0 * 3 + 2];
                    float dx1 = dirS[r1 * 3], dy1 = dirS[r1 * 3 + 1], dz1 = dirS[r1 * 3 + 2];
#pragma unroll
                    for (int t = 0; t < 4; ++t) {
                        const int col = n0 - 128 + t * 8 + tig * 2;
                        float bb0 = __ldg(bv + col), bb1 = __ldg(bv + col + 1);
                        if (d0 >= 0) {
                            float v0 = acc[mb][t][0] + bb0, v1 = acc[mb][t][1] + bb1;
                            float* vb = out_v + (long long)d0 * 3 * FDIM + col;
                            red2(vb, dx0 * v0, dx0 * v1);
                            red2(vb + FDIM, dy0 * v0, dy0 * v1);
                            red2(vb + 2 * FDIM, dz0 * v0, dz0 * v1);
                        }
                        if (d1 >= 0) {
                            float v0 = acc[mb][t][2] + bb0, v1 = acc[mb][t][3] + bb1;
                            float* vb = out_v + (long long)d1 * 3 * FDIM + col;
                            red2(vb, dx1 * v0, dx1 * v1);
                            red2(vb + FDIM, dy1 * v0, dy1 * v1);
                            red2(vb + 2 * FDIM, dz1 * v0, dz1 * v1);
                        }
                    }
                }
            }
        }
    }
}

// ---------------- launcher ----------------
extern "C" void kernel_launch(void* const* d_in, const int* in_sizes, int n_in,
                              void* d_out, int out_size) {
    const float* s       = (const float*)d_in[0];
    const float* v       = (const float*)d_in[1];
    const float* pos     = (const float*)d_in[2];
    const void*  eidx    = d_in[3];
    const float* W1      = (const float*)d_in[4];
    const float* b1      = (const float*)d_in[5];
    const float* W2      = (const float*)d_in[6];
    const float* b2      = (const float*)d_in[7];
    const float* Ws      = (const float*)d_in[8];
    const float* bs      = (const float*)d_in[9];
    const float* Wv      = (const float*)d_in[10];
    const float* bv      = (const float*)d_in[11];
    const float* centers = (const float*)d_in[12];
    const float* widths  = (const float*)d_in[13];

    int N = in_sizes[0] / FDIM;
    int E = in_sizes[3] / 2;

    float* out_s = (float*)d_out;
    float* out_v = out_s + (long long)N * FDIM;

    detect_idx_kernel<<<1, 256>>>((const int*)eidx);

    int ns4 = N * FDIM / 4;
    int nv4 = N * 3 * FDIM / 4;
    init_out_kernel<<<1024, 256>>>((const float4*)s, (const float4*)v, (float4*)d_out, ns4, nv4);

    prep_weights<<<256, 256>>>(W1, W2, Ws, Wv);

    cudaFuncSetAttribute(painn_mma_kernel, cudaFuncAttributeMaxDynamicSharedMemorySize,
                         SMEM_TOTAL);

    int grid = (E + TILE_E - 1) / TILE_E;
    painn_mma_kernel<<<grid, NTHREADS, SMEM_TOTAL>>>(s, pos, eidx, b1, b2, bs, bv, centers,
                                                     widths, out_s, out_v, E);
}